// round 15
// baseline (speedup 1.0000x reference)
#include <cuda_runtime.h>
#include <cuda_fp16.h>
#include <math.h>
#include <cstdint>

// Problem constants
#define B_ 16
#define CDIM 256
#define H_ 128
#define W_ 128
#define NTOK 262144   // B*H*W tokens

// Scratch (device globals)
__device__ float  g_tok[67108864];     // [NTOK, 256] fp32 residual stream
__device__ __half g_yh[67108864];      // [NTOK, 256] LN output fp16
__device__ __half g_qkvh[201326592];   // [NTOK, 768] fp16
__device__ __half g_oh[67108864];      // [NTOK, 256] fp16
__device__ __half g_wh[786432];        // qkv_w|proj_w|fc1_w|fc2_w fp16

#define WOFF_QKV 0
#define WOFF_PROJ 196608
#define WOFF_FC1 262144
#define WOFF_FC2 524288

__device__ __forceinline__ float gelu_exact(float v) {
    return 0.5f * v * (1.0f + erff(v * 0.70710678118654752f));
}

__device__ __forceinline__ uint32_t h2_u32(__half2 v) {
    return *reinterpret_cast<uint32_t*>(&v);
}

__device__ __forceinline__ void cpa16(uint32_t dst, const void* src) {
    asm volatile("cp.async.cg.shared.global [%0], [%1], 16;" :: "r"(dst), "l"(src));
}
#define CP_COMMIT() asm volatile("cp.async.commit_group;" ::: "memory")
#define CP_WAIT1()  asm volatile("cp.async.wait_group 1;" ::: "memory")
#define CP_WAIT2()  asm volatile("cp.async.wait_group 2;" ::: "memory")

#define MMA_H(dd, a0, a1, a2, a3, b0, b1) \
    asm volatile( \
        "mma.sync.aligned.m16n8k16.row.col.f32.f16.f16.f32 " \
        "{%0,%1,%2,%3}, {%4,%5,%6,%7}, {%8,%9}, {%0,%1,%2,%3};" \
        : "+f"((dd)[0]), "+f"((dd)[1]), "+f"((dd)[2]), "+f"((dd)[3]) \
        : "r"(a0), "r"(a1), "r"(a2), "r"(a3), "r"(b0), "r"(b1))

#define LDSM_X4(r0, r1, r2, r3, addr) \
    asm volatile("ldmatrix.sync.aligned.m8n8.x4.shared.b16 {%0,%1,%2,%3}, [%4];" \
        : "=r"(r0), "=r"(r1), "=r"(r2), "=r"(r3) : "r"(addr))

// ===========================================================================
// Weight conversion fp32 -> fp16
// ===========================================================================
__global__ void __launch_bounds__(256) cvt_weights(const float* __restrict__ qkv_w,
                                                   const float* __restrict__ proj_w,
                                                   const float* __restrict__ fc1_w,
                                                   const float* __restrict__ fc2_w) {
    for (int i = blockIdx.x * 256 + threadIdx.x; i < 786432; i += gridDim.x * 256) {
        float v;
        if (i < WOFF_PROJ)      v = qkv_w[i - WOFF_QKV];
        else if (i < WOFF_FC1)  v = proj_w[i - WOFF_PROJ];
        else if (i < WOFF_FC2)  v = fc1_w[i - WOFF_FC1];
        else                    v = fc2_w[i - WOFF_FC2];
        g_wh[i] = __float2half_rn(v);
    }
}

// ===========================================================================
// FP16 mma.sync GEMM (qkv only now). EPI 0 = bias -> f16.
// ===========================================================================
template <int EPI>
__global__ void __launch_bounds__(256, 2) mma_gemm_h(const __half* __restrict__ A,
                                                     const __half* __restrict__ Wm,
                                                     const float* __restrict__ bias,
                                                     void* __restrict__ OutV,
                                                     int N, int K) {
    extern __shared__ uint32_t sm[];
    uint32_t* As = sm;
    uint32_t* Bs = sm + 12288;

    const int tid = threadIdx.x;
    const int wid = tid >> 5;
    const int lane = tid & 31;
    const long long m0 = (long long)blockIdx.y * 128;
    const int n0 = blockIdx.x * 128;

    const int wm = (wid >> 2) * 64;
    const int wn = (wid & 3) * 32;
    const int lm = lane >> 2;
    const int lk = lane & 3;

    const uint32_t as_b = (uint32_t)__cvta_generic_to_shared(As);
    const uint32_t bs_b = (uint32_t)__cvta_generic_to_shared(Bs);

    uint32_t soff[4];
    const __half* aptr[4];
    const __half* bptr[4];
#pragma unroll
    for (int j = 0; j < 4; j++) {
        const int id = tid + 256 * j;
        const int row = id >> 3;
        const int seg = id & 7;
        soff[j] = (uint32_t)(row * 32 + ((seg * 4) ^ ((row & 7) * 4))) * 4u;
        aptr[j] = A + (m0 + row) * (long long)K + seg * 8;
        bptr[j] = Wm + (long long)(n0 + row) * K + seg * 8;
    }

    const int KT = K >> 6;

#pragma unroll
    for (int s = 0; s < 2; s++) {
        const uint32_t sb = s * 16384u;
#pragma unroll
        for (int j = 0; j < 4; j++) {
            cpa16(as_b + sb + soff[j], aptr[j] + s * 64);
            cpa16(bs_b + sb + soff[j], bptr[j] + s * 64);
        }
        CP_COMMIT();
    }

    const int l8 = lane & 7;
    const int subm = (lane >> 3) & 1;
    const int subk = lane >> 4;
    uint32_t aRowOff[4], aSwz[4];
#pragma unroll
    for (int mf = 0; mf < 4; mf++) {
        const int rowA = wm + mf * 16 + subm * 8 + l8;
        aRowOff[mf] = (uint32_t)rowA * 32;
        aSwz[mf] = (uint32_t)(rowA & 7) * 4;
    }
    uint32_t bRowOff[2], bSwz[2];
#pragma unroll
    for (int p = 0; p < 2; p++) {
        const int rowB = wn + p * 16 + subk * 8 + l8;
        bRowOff[p] = (uint32_t)rowB * 32;
        bSwz[p] = (uint32_t)(rowB & 7) * 4;
    }

    float d[4][4][4];
#pragma unroll
    for (int i = 0; i < 4; i++)
#pragma unroll
        for (int j = 0; j < 4; j++)
#pragma unroll
            for (int q = 0; q < 4; q++) d[i][j][q] = 0.0f;

    int stage = 0;
    for (int kt = 0; kt < KT; kt++) {
        CP_WAIT1();
        __syncthreads();

        if (kt + 2 < KT) {
            const int s2 = stage + 2 >= 3 ? stage - 1 : stage + 2;
            const int ko = (kt + 2) * 64;
            const uint32_t sb = s2 * 16384u;
#pragma unroll
            for (int j = 0; j < 4; j++) {
                cpa16(as_b + sb + soff[j], aptr[j] + ko);
                cpa16(bs_b + sb + soff[j], bptr[j] + ko);
            }
        }
        CP_COMMIT();

        const uint32_t aBase = as_b + stage * 16384u;
        const uint32_t bBase = bs_b + stage * 16384u;
#pragma unroll
        for (int ks = 0; ks < 4; ks++) {
            const uint32_t kcA = (uint32_t)(ks * 8 + subk * 4);
            const uint32_t kcB = (uint32_t)(ks * 8 + subm * 4);
            uint32_t a[4][4];
#pragma unroll
            for (int mf = 0; mf < 4; mf++) {
                const uint32_t addr = aBase + (aRowOff[mf] + (kcA ^ aSwz[mf])) * 4u;
                LDSM_X4(a[mf][0], a[mf][1], a[mf][2], a[mf][3], addr);
            }
            uint32_t b[4][2];
#pragma unroll
            for (int p = 0; p < 2; p++) {
                const uint32_t addr = bBase + (bRowOff[p] + (kcB ^ bSwz[p])) * 4u;
                LDSM_X4(b[2 * p][0], b[2 * p][1], b[2 * p + 1][0], b[2 * p + 1][1], addr);
            }
#pragma unroll
            for (int mf = 0; mf < 4; mf++)
#pragma unroll
                for (int nf = 0; nf < 4; nf++)
                    MMA_H(d[mf][nf], a[mf][0], a[mf][1], a[mf][2], a[mf][3],
                          b[nf][0], b[nf][1]);
        }
        stage = stage + 1 >= 3 ? 0 : stage + 1;
    }

#pragma unroll
    for (int nf = 0; nf < 4; nf++) {
        const int gcol = n0 + wn + nf * 8 + 2 * lk;
        const float2 bv = *(const float2*)&bias[gcol];
#pragma unroll
        for (int mf = 0; mf < 4; mf++) {
            const long long row = m0 + wm + mf * 16 + lm;
            float2 v0, v1;
            v0.x = d[mf][nf][0] + bv.x;
            v0.y = d[mf][nf][1] + bv.y;
            v1.x = d[mf][nf][2] + bv.x;
            v1.y = d[mf][nf][3] + bv.y;
            __half* Out = (__half*)OutV;
            *(__half2*)&Out[row * (long long)N + gcol] = __floats2half2_rn(v0.x, v0.y);
            *(__half2*)&Out[(row + 8) * (long long)N + gcol] = __floats2half2_rn(v1.x, v1.y);
        }
    }
}

// ===========================================================================
// Fused MLP: fc1 + bias + GELU + fc2 + bias + residual + scatter NCHW.
// One 512-thread CTA per 128-row M-tile. yh tile resident (64KB),
// hid computed in 8 chunks of 128 cols via smem (32KB), weights streamed
// through a 4-slot x 32KB cp.async ring. D2[128x256] in registers.
// ===========================================================================
#define MLP_SA 0            // u32: 4 subtiles x 4096 (64KB)
#define MLP_RING 16384      // u32: 4 slots x 8192 (128KB)
#define MLP_HID 49152       // u32: 2 subtiles x 4096 (32KB)
#define MLP_SMEM (57344 * 4)

__global__ void __launch_bounds__(512) mlp_fused(const __half* __restrict__ A,
                                                 const __half* __restrict__ w1,
                                                 const __half* __restrict__ w2,
                                                 const float* __restrict__ b1,
                                                 const float* __restrict__ b2,
                                                 const float* __restrict__ tok,
                                                 float* __restrict__ Out) {
    extern __shared__ uint32_t sm[];
    const uint32_t smb = (uint32_t)__cvta_generic_to_shared(sm);
    const uint32_t ring_b = smb + MLP_RING * 4u;

    const int tid = threadIdx.x;
    const int wid = tid >> 5;
    const int lane = tid & 31;
    const long long m0 = (long long)blockIdx.x * 128;

    const int wr = wid >> 2;          // m: rows wr*32..+32 (both phases)
    const int wc = wid & 3;           // fc1: cols wc*32; fc2: cols wc*64
    const int lm = lane >> 2;
    const int lk = lane & 3;
    const int l8 = lane & 7;
    const int subm = (lane >> 3) & 1;
    const int subk = lane >> 4;

    // ---- stage yh A tile [128][256]h into 4 k-subtiles ----
#pragma unroll
    for (int j = 0; j < 8; j++) {
        const int id = tid + 512 * j;
        const int row = id >> 5;
        const int seg = id & 31;
        const int kt = seg >> 3, segk = seg & 7;
        const uint32_t off = (uint32_t)(kt * 4096 + row * 32 + ((segk * 4) ^ ((row & 7) * 4))) * 4u;
        cpa16(smb + off, A + (m0 + row) * 256LL + kt * 64 + segk * 8);
    }
    CP_COMMIT();

    // ---- issue loads q=0,1,2 ----
#pragma unroll
    for (int qq = 0; qq < 3; qq++) {
        const uint32_t slot = ring_b + (uint32_t)(qq & 3) * 32768u;
        // q<4 of chunk 0 are all W1 stages (jj = qq)
#pragma unroll
        for (int j = 0; j < 2; j++) {
            const int id = tid + 512 * j;
            const int row = id >> 3, segk = id & 7;
            const uint32_t off = (uint32_t)(row * 32 + ((segk * 4) ^ ((row & 7) * 4))) * 4u;
            cpa16(slot + off, w1 + (long long)row * 256 + qq * 64 + segk * 8);
        }
        CP_COMMIT();
    }

    // fragment address components
    uint32_t aRowOff[2], aSwz[2];
#pragma unroll
    for (int mf = 0; mf < 2; mf++) {
        const int rowA = wr * 32 + mf * 16 + subm * 8 + l8;
        aRowOff[mf] = (uint32_t)rowA * 32;
        aSwz[mf] = (uint32_t)(rowA & 7) * 4;
    }
    // fc1 B rows (32-wide warp tile)
    uint32_t b1RowOff[2], b1Swz[2];
#pragma unroll
    for (int p = 0; p < 2; p++) {
        const int rowB = wc * 32 + p * 16 + subk * 8 + l8;
        b1RowOff[p] = (uint32_t)rowB * 32;
        b1Swz[p] = (uint32_t)(rowB & 7) * 4;
    }
    // fc2 B rows (64-wide warp tile)
    uint32_t b2RowOff[4], b2Swz[4];
#pragma unroll
    for (int p = 0; p < 4; p++) {
        const int rowB = wc * 64 + p * 16 + subk * 8 + l8;
        b2RowOff[p] = (uint32_t)rowB * 32;
        b2Swz[p] = (uint32_t)(rowB & 7) * 4;
    }

    float d2[2][8][4];
#pragma unroll
    for (int i = 0; i < 2; i++)
#pragma unroll
        for (int j = 0; j < 8; j++)
#pragma unroll
            for (int q = 0; q < 4; q++) d2[i][j][q] = 0.0f;

    int qn = 3;
    int q = 0;
    for (int c = 0; c < 8; c++) {
        float d1[2][4][4];
#pragma unroll
        for (int i = 0; i < 2; i++)
#pragma unroll
            for (int j = 0; j < 4; j++)
#pragma unroll
                for (int p = 0; p < 4; p++) d1[i][j][p] = 0.0f;

        // ---- fc1: 4 W1 k-stages ----
        for (int kt = 0; kt < 4; kt++) {
            CP_WAIT2();
            __syncthreads();
            // issue load qn
            if (qn < 48) {
                const int cc = qn / 6, jj = qn % 6;
                const uint32_t slot = ring_b + (uint32_t)(qn & 3) * 32768u;
                if (jj < 4) {
#pragma unroll
                    for (int j = 0; j < 2; j++) {
                        const int id = tid + 512 * j;
                        const int row = id >> 3, segk = id & 7;
                        const uint32_t off = (uint32_t)(row * 32 + ((segk * 4) ^ ((row & 7) * 4))) * 4u;
                        cpa16(slot + off, w1 + (long long)(cc * 128 + row) * 256 + jj * 64 + segk * 8);
                    }
                } else {
                    const int kt2 = jj - 4;
#pragma unroll
                    for (int j = 0; j < 4; j++) {
                        const int id = tid + 512 * j;
                        const int row = id >> 3, segk = id & 7;
                        const uint32_t off = (uint32_t)(row * 32 + ((segk * 4) ^ ((row & 7) * 4))) * 4u;
                        cpa16(slot + off, w2 + (long long)row * 1024 + cc * 128 + kt2 * 64 + segk * 8);
                    }
                }
            }
            CP_COMMIT();
            qn++;

            const uint32_t slotB = ring_b + (uint32_t)(q & 3) * 32768u;
            const uint32_t aBase = smb + (uint32_t)kt * 16384u;
#pragma unroll
            for (int ks = 0; ks < 4; ks++) {
                const uint32_t kcA = (uint32_t)(ks * 8 + subk * 4);
                const uint32_t kcB = (uint32_t)(ks * 8 + subm * 4);
                uint32_t a[2][4];
#pragma unroll
                for (int mf = 0; mf < 2; mf++) {
                    const uint32_t addr = aBase + (aRowOff[mf] + (kcA ^ aSwz[mf])) * 4u;
                    LDSM_X4(a[mf][0], a[mf][1], a[mf][2], a[mf][3], addr);
                }
                uint32_t b[4][2];
#pragma unroll
                for (int p = 0; p < 2; p++) {
                    const uint32_t addr = slotB + (b1RowOff[p] + (kcB ^ b1Swz[p])) * 4u;
                    LDSM_X4(b[2 * p][0], b[2 * p][1], b[2 * p + 1][0], b[2 * p + 1][1], addr);
                }
#pragma unroll
                for (int mf = 0; mf < 2; mf++)
#pragma unroll
                    for (int nf = 0; nf < 4; nf++)
                        MMA_H(d1[mf][nf], a[mf][0], a[mf][1], a[mf][2], a[mf][3],
                              b[nf][0], b[nf][1]);
            }
            q++;
        }

        // ---- bias + GELU -> fp16 -> sHid ----
#pragma unroll
        for (int nt = 0; nt < 4; nt++) {
            const int lc = wc * 32 + nt * 8 + 2 * lk;  // 0..127
            const float2 bb = *(const float2*)&b1[c * 128 + lc];
            const int sub = lc >> 6;
            const uint32_t u = (uint32_t)((lc & 63) >> 1);
#pragma unroll
            for (int mt = 0; mt < 2; mt++) {
                const int r0 = wr * 32 + mt * 16 + lm;
                const int r1 = r0 + 8;
                float g0x = gelu_exact(d1[mt][nt][0] + bb.x);
                float g0y = gelu_exact(d1[mt][nt][1] + bb.y);
                float g1x = gelu_exact(d1[mt][nt][2] + bb.x);
                float g1y = gelu_exact(d1[mt][nt][3] + bb.y);
                sm[MLP_HID + sub * 4096 + r0 * 32 + (u ^ ((uint32_t)(r0 & 7) * 4))] =
                    h2_u32(__floats2half2_rn(g0x, g0y));
                sm[MLP_HID + sub * 4096 + r1 * 32 + (u ^ ((uint32_t)(r1 & 7) * 4))] =
                    h2_u32(__floats2half2_rn(g1x, g1y));
            }
        }

        // ---- fc2 partial: 2 W2 k-stages (K=128) ----
        for (int kt2 = 0; kt2 < 2; kt2++) {
            CP_WAIT2();
            __syncthreads();   // publishes sHid too
            if (qn < 48) {
                const int cc = qn / 6, jj = qn % 6;
                const uint32_t slot = ring_b + (uint32_t)(qn & 3) * 32768u;
                if (jj < 4) {
#pragma unroll
                    for (int j = 0; j < 2; j++) {
                        const int id = tid + 512 * j;
                        const int row = id >> 3, segk = id & 7;
                        const uint32_t off = (uint32_t)(row * 32 + ((segk * 4) ^ ((row & 7) * 4))) * 4u;
                        cpa16(slot + off, w1 + (long long)(cc * 128 + row) * 256 + jj * 64 + segk * 8);
                    }
                } else {
                    const int kt2n = jj - 4;
#pragma unroll
                    for (int j = 0; j < 4; j++) {
                        const int id = tid + 512 * j;
                        const int row = id >> 3, segk = id & 7;
                        const uint32_t off = (uint32_t)(row * 32 + ((segk * 4) ^ ((row & 7) * 4))) * 4u;
                        cpa16(slot + off, w2 + (long long)row * 1024 + cc * 128 + kt2n * 64 + segk * 8);
                    }
                }
            }
            CP_COMMIT();
            qn++;

            const uint32_t slotB = ring_b + (uint32_t)(q & 3) * 32768u;
            const uint32_t aBase = smb + (uint32_t)(MLP_HID + kt2 * 4096) * 4u;
#pragma unroll
            for (int ks = 0; ks < 4; ks++) {
                const uint32_t kcA = (uint32_t)(ks * 8 + subk * 4);
                const uint32_t kcB = (uint32_t)(ks * 8 + subm * 4);
                uint32_t a[2][4];
#pragma unroll
                for (int mf = 0; mf < 2; mf++) {
                    const uint32_t addr = aBase + (aRowOff[mf] + (kcA ^ aSwz[mf])) * 4u;
                    LDSM_X4(a[mf][0], a[mf][1], a[mf][2], a[mf][3], addr);
                }
                uint32_t b[8][2];
#pragma unroll
                for (int p = 0; p < 4; p++) {
                    const uint32_t addr = slotB + (b2RowOff[p] + (kcB ^ b2Swz[p])) * 4u;
                    LDSM_X4(b[2 * p][0], b[2 * p][1], b[2 * p + 1][0], b[2 * p + 1][1], addr);
                }
#pragma unroll
                for (int mf = 0; mf < 2; mf++)
#pragma unroll
                    for (int nf = 0; nf < 8; nf++)
                        MMA_H(d2[mf][nf], a[mf][0], a[mf][1], a[mf][2], a[mf][3],
                              b[nf][0], b[nf][1]);
            }
            q++;
        }
    }

    // ---- epilogue: bias2 + residual + scatter NCHW ----
#pragma unroll
    for (int nf = 0; nf < 8; nf++) {
        const int gcol = wc * 64 + nf * 8 + 2 * lk;
        const float2 bv = *(const float2*)&b2[gcol];
#pragma unroll
        for (int mf = 0; mf < 2; mf++) {
            const long long row = m0 + wr * 32 + mf * 16 + lm;
            float2 r0 = *(const float2*)&tok[row * 256 + gcol];
            float2 r1 = *(const float2*)&tok[(row + 8) * 256 + gcol];
            float2 v0, v1;
            v0.x = d2[mf][nf][0] + bv.x + r0.x;
            v0.y = d2[mf][nf][1] + bv.y + r0.y;
            v1.x = d2[mf][nf][2] + bv.x + r1.x;
            v1.y = d2[mf][nf][3] + bv.y + r1.y;
            const int n_ = (int)(row >> 6);
            const int t_ = (int)(row & 63);
            const int bb = n_ >> 8, wy = (n_ >> 4) & 15, wx = n_ & 15;
            const int hh = wy * 8 + (t_ >> 3), ww = wx * 8 + (t_ & 7);
            const long long base0 = ((long long)(bb * 256 + gcol) << 14) + hh * 128 + ww;
            Out[base0] = v0.x;
            Out[base0 + 16384] = v0.y;
            Out[base0 + 128] = v1.x;
            Out[base0 + 16384 + 128] = v1.y;
        }
    }
}

// ===========================================================================
// Fused proj GEMM + residual + LN2 (unchanged from R14)
// ===========================================================================
#define PROJ_SMEM (147456 + 4096 + 1024)

__global__ void __launch_bounds__(512) proj_ln(const __half* __restrict__ A,
                                               const __half* __restrict__ Wm,
                                               const float* __restrict__ bias,
                                               float* __restrict__ tok,
                                               const float* __restrict__ g2,
                                               const float* __restrict__ b2,
                                               __half* __restrict__ yh) {
    extern __shared__ uint32_t sm[];
    uint32_t* As = sm;
    uint32_t* Bs = sm + 12288;
    float* spart = (float*)(sm + 36864);
    float* smr   = spart + 1024;

    const int tid = threadIdx.x;
    const int wid = tid >> 5;
    const int lane = tid & 31;
    const long long m0 = (long long)blockIdx.x * 128;

    const int wr = wid >> 2;
    const int wc = wid & 3;
    const int lm = lane >> 2;
    const int lk = lane & 3;

    const uint32_t as_b = (uint32_t)__cvta_generic_to_shared(As);
    const uint32_t bs_b = (uint32_t)__cvta_generic_to_shared(Bs);

    uint32_t aoff[2];
    const __half* aptr[2];
#pragma unroll
    for (int j = 0; j < 2; j++) {
        const int id = tid + 512 * j;
        const int row = id >> 3;
        const int seg = id & 7;
        aoff[j] = (uint32_t)(row * 32 + ((seg * 4) ^ ((row & 7) * 4))) * 4u;
        aptr[j] = A + (m0 + row) * 256LL + seg * 8;
    }
    uint32_t boff[4];
    const __half* bptr[4];
#pragma unroll
    for (int j = 0; j < 4; j++) {
        const int id = tid + 512 * j;
        const int row = id >> 3;
        const int seg = id & 7;
        boff[j] = (uint32_t)(row * 32 + ((seg * 4) ^ ((row & 7) * 4))) * 4u;
        bptr[j] = Wm + (long long)row * 256 + seg * 8;
    }

#pragma unroll
    for (int s = 0; s < 2; s++) {
        const uint32_t sbA = s * 16384u;
        const uint32_t sbB = s * 32768u;
#pragma unroll
        for (int j = 0; j < 2; j++) cpa16(as_b + sbA + aoff[j], aptr[j] + s * 64);
#pragma unroll
        for (int j = 0; j < 4; j++) cpa16(bs_b + sbB + boff[j], bptr[j] + s * 64);
        CP_COMMIT();
    }

    const int l8 = lane & 7;
    const int subm = (lane >> 3) & 1;
    const int subk = lane >> 4;
    uint32_t aRowOff[2], aSwz[2];
#pragma unroll
    for (int mf = 0; mf < 2; mf++) {
        const int rowA = wr * 32 + mf * 16 + subm * 8 + l8;
        aRowOff[mf] = (uint32_t)rowA * 32;
        aSwz[mf] = (uint32_t)(rowA & 7) * 4;
    }
    uint32_t bRowOff[4], bSwz[4];
#pragma unroll
    for (int p = 0; p < 4; p++) {
        const int rowB = wc * 64 + p * 16 + subk * 8 + l8;
        bRowOff[p] = (uint32_t)rowB * 32;
        bSwz[p] = (uint32_t)(rowB & 7) * 4;
    }

    float d[2][8][4];
#pragma unroll
    for (int i = 0; i < 2; i++)
#pragma unroll
        for (int j = 0; j < 8; j++)
#pragma unroll
            for (int q = 0; q < 4; q++) d[i][j][q] = 0.0f;

    int stage = 0;
    for (int kt = 0; kt < 4; kt++) {
        CP_WAIT1();
        __syncthreads();

        if (kt + 2 < 4) {
            const int s2 = stage + 2 >= 3 ? stage - 1 : stage + 2;
            const int ko = (kt + 2) * 64;
            const uint32_t sbA = s2 * 16384u;
            const uint32_t sbB = s2 * 32768u;
#pragma unroll
            for (int j = 0; j < 2; j++) cpa16(as_b + sbA + aoff[j], aptr[j] + ko);
#pragma unroll
            for (int j = 0; j < 4; j++) cpa16(bs_b + sbB + boff[j], bptr[j] + ko);
        }
        CP_COMMIT();

        const uint32_t aBase = as_b + stage * 16384u;
        const uint32_t bBase = bs_b + stage * 32768u;
#pragma unroll
        for (int ks = 0; ks < 4; ks++) {
            const uint32_t kcA = (uint32_t)(ks * 8 + subk * 4);
            const uint32_t kcB = (uint32_t)(ks * 8 + subm * 4);
            uint32_t a[2][4];
#pragma unroll
            for (int mf = 0; mf < 2; mf++) {
                const uint32_t addr = aBase + (aRowOff[mf] + (kcA ^ aSwz[mf])) * 4u;
                LDSM_X4(a[mf][0], a[mf][1], a[mf][2], a[mf][3], addr);
            }
            uint32_t b[8][2];
#pragma unroll
            for (int p = 0; p < 4; p++) {
                const uint32_t addr = bBase + (bRowOff[p] + (kcB ^ bSwz[p])) * 4u;
                LDSM_X4(b[2 * p][0], b[2 * p][1], b[2 * p + 1][0], b[2 * p + 1][1], addr);
            }
#pragma unroll
            for (int mf = 0; mf < 2; mf++)
#pragma unroll
                for (int nf = 0; nf < 8; nf++)
                    MMA_H(d[mf][nf], a[mf][0], a[mf][1], a[mf][2], a[mf][3],
                          b[nf][0], b[nf][1]);
        }
        stage = stage + 1 >= 3 ? 0 : stage + 1;
    }

    float rsum[2][2], rsq[2][2];
#pragma unroll
    for (int i = 0; i < 2; i++) { rsum[i][0] = rsum[i][1] = 0.0f; rsq[i][0] = rsq[i][1] = 0.0f; }

#pragma unroll
    for (int nf = 0; nf < 8; nf++) {
        const int gcol = wc * 64 + nf * 8 + 2 * lk;
        const float2 bv = *(const float2*)&bias[gcol];
#pragma unroll
        for (int mf = 0; mf < 2; mf++) {
            const long long r0 = m0 + wr * 32 + mf * 16 + lm;
            float2 q0 = *(const float2*)&tok[r0 * 256 + gcol];
            float2 q1 = *(const float2*)&tok[(r0 + 8) * 256 + gcol];
            float2 v0, v1;
            v0.x = d[mf][nf][0] + bv.x + q0.x;
            v0.y = d[mf][nf][1] + bv.y + q0.y;
            v1.x = d[mf][nf][2] + bv.x + q1.x;
            v1.y = d[mf][nf][3] + bv.y + q1.y;
            d[mf][nf][0] = v0.x; d[mf][nf][1] = v0.y;
            d[mf][nf][2] = v1.x; d[mf][nf][3] = v1.y;
            *(float2*)&tok[r0 * 256 + gcol] = v0;
            *(float2*)&tok[(r0 + 8) * 256 + gcol] = v1;
            rsum[mf][0] += v0.x + v0.y;  rsq[mf][0] += v0.x * v0.x + v0.y * v0.y;
            rsum[mf][1] += v1.x + v1.y;  rsq[mf][1] += v1.x * v1.x + v1.y * v1.y;
        }
    }
#pragma unroll
    for (int mf = 0; mf < 2; mf++)
#pragma unroll
        for (int s = 0; s < 2; s++) {
            rsum[mf][s] += __shfl_xor_sync(0xFFFFFFFFu, rsum[mf][s], 1);
            rsum[mf][s] += __shfl_xor_sync(0xFFFFFFFFu, rsum[mf][s], 2);
            rsq[mf][s]  += __shfl_xor_sync(0xFFFFFFFFu, rsq[mf][s], 1);
            rsq[mf][s]  += __shfl_xor_sync(0xFFFFFFFFu, rsq[mf][s], 2);
        }
    if (lk == 0) {
#pragma unroll
        for (int mf = 0; mf < 2; mf++)
#pragma unroll
            for (int s = 0; s < 2; s++) {
                const int r = wr * 32 + mf * 16 + s * 8 + lm;
                spart[(r * 4 + wc) * 2] = rsum[mf][s];
                spart[(r * 4 + wc) * 2 + 1] = rsq[mf][s];
            }
    }
    __syncthreads();
    if (tid < 128) {
        float s = 0.0f, q = 0.0f;
#pragma unroll
        for (int c = 0; c < 4; c++) {
            s += spart[(tid * 4 + c) * 2];
            q += spart[(tid * 4 + c) * 2 + 1];
        }
        const float mu = s * (1.0f / 256.0f);
        const float var = q * (1.0f / 256.0f) - mu * mu;
        smr[tid * 2] = mu;
        smr[tid * 2 + 1] = rsqrtf(var + 1e-5f);
    }
    __syncthreads();

#pragma unroll
    for (int nf = 0; nf < 8; nf++) {
        const int gcol = wc * 64 + nf * 8 + 2 * lk;
        const float2 gv = *(const float2*)&g2[gcol];
        const float2 bv = *(const float2*)&b2[gcol];
#pragma unroll
        for (int mf = 0; mf < 2; mf++) {
            const int rl0 = wr * 32 + mf * 16 + lm;
            const float mu0 = smr[rl0 * 2],       ri0 = smr[rl0 * 2 + 1];
            const float mu1 = smr[(rl0 + 8) * 2], ri1 = smr[(rl0 + 8) * 2 + 1];
            const long long r0 = m0 + rl0;
            __half2 h0 = __floats2half2_rn((d[mf][nf][0] - mu0) * ri0 * gv.x + bv.x,
                                           (d[mf][nf][1] - mu0) * ri0 * gv.y + bv.y);
            __half2 h1 = __floats2half2_rn((d[mf][nf][2] - mu1) * ri1 * gv.x + bv.x,
                                           (d[mf][nf][3] - mu1) * ri1 * gv.y + bv.y);
            *(__half2*)&yh[r0 * 256 + gcol] = h0;
            *(__half2*)&yh[(r0 + 8) * 256 + gcol] = h1;
        }
    }
}

// ===========================================================================
// Fused gather + LN1 (unchanged)
// ===========================================================================
__global__ void __launch_bounds__(256) gather_ln(const float* __restrict__ x,
                                                 const float* __restrict__ g,
                                                 const float* __restrict__ b,
                                                 float* __restrict__ tok,
                                                 __half* __restrict__ yh) {
    extern __shared__ float st[];

    const int tid = threadIdx.x;
    const int n = blockIdx.x;
    const int bb = n >> 8, wy = (n >> 4) & 15, wx = n & 15;

#pragma unroll
    for (int j = 0; j < 8; j++) {
        const int p = tid + 256 * j;
        const int c = p >> 3;
        const int iy = p & 7;
        const float* xp = x + (((long long)(bb * 256 + c)) << 14)
                        + (wy * 8 + iy) * 128 + wx * 8;
        float4 u0 = *(const float4*)xp;
        float4 u1 = *(const float4*)(xp + 4);
        const int cs = c ^ (iy * 4);
        float* row0 = st + (iy * 8) * 256;
        row0[0 * 256 + cs] = u0.x;
        row0[1 * 256 + cs] = u0.y;
        row0[2 * 256 + cs] = u0.z;
        row0[3 * 256 + cs] = u0.w;
        row0[4 * 256 + cs] = u1.x;
        row0[5 * 256 + cs] = u1.y;
        row0[6 * 256 + cs] = u1.z;
        row0[7 * 256 + cs] = u1.w;
    }
    __syncthreads();

    const int w = tid >> 5, lane = tid & 31;
#pragma unroll
    for (int r = 0; r < 8; r++) {
        const int t = w * 8 + r;
        const int xr = ((t >> 3) & 7) * 4;
        const float* row = st + t * 256;
        float4 v0 = *(const float4*)&row[(4 * lane) ^ xr];
        float4 v1 = *(const float4*)&row[(128 + 4 * lane) ^ xr];

        float s = v0.x + v0.y + v0.z + v0.w + v1.x + v1.y + v1.z + v1.w;
#pragma unroll
        for (int o = 16; o; o >>= 1) s += __shfl_xor_sync(0xFFFFFFFFu, s, o);
        const float mu = s * (1.0f / 256.0f);

        float q = (v0.x - mu) * (v0.x - mu) + (v0.y - mu) * (v0.y - mu)
                + (v0.z - mu) * (v0.z - mu) + (v0.w - mu) * (v0.w - mu)
                + (v1.x - mu) * (v1.x - mu) + (v1.y - mu) * (v1.y - mu)
                + (v1.z - mu) * (v1.z - mu) + (v1.w - mu) * (v1.w - mu);
#pragma unroll
        for (int o = 16; o; o >>= 1) q += __shfl_xor_sync(0xFFFFFFFFu, q, o);
        const float rinv = rsqrtf(q * (1.0f / 256.0f) + 1e-5f);

        const long long grow = (long long)n * 64 + t;
        *(float4*)&tok[grow * CDIM + 4 * lane] = v0;
        *(float4*)&tok[grow * CDIM + 128 + 4 * lane] = v1;

        float4 g0 = *(const float4*)&g[4 * lane];
        float4 g1 = *(const float4*)&g[128 + 4 * lane];
        float4 b0 = *(const float4*)&b[4 * lane];
        float4 b1 = *(const float4*)&b[128 + 4 * lane];
        __half* yrow = yh + grow * CDIM;
        *(__half2*)&yrow[4 * lane] = __floats2half2_rn((v0.x - mu) * rinv * g0.x + b0.x,
                                                       (v0.y - mu) * rinv * g0.y + b0.y);
        *(__half2*)&yrow[4 * lane + 2] = __floats2half2_rn((v0.z - mu) * rinv * g0.z + b0.z,
                                                           (v0.w - mu) * rinv * g0.w + b0.w);
        *(__half2*)&yrow[128 + 4 * lane] = __floats2half2_rn((v1.x - mu) * rinv * g1.x + b1.x,
                                                             (v1.y - mu) * rinv * g1.y + b1.y);
        *(__half2*)&yrow[128 + 4 * lane + 2] = __floats2half2_rn((v1.z - mu) * rinv * g1.z + b1.z,
                                                                 (v1.w - mu) * rinv * g1.w + b1.w);
    }
}

// ===========================================================================
// Tensor-core window attention (unchanged from R14 fixed version)
// ===========================================================================
#define SQK2 264
#define SVT2 70
#define SVT2_H 2240
#define ATTN_SMEM ((64 * SQK2 + 4 * SVT2_H) * 2)

__global__ void __launch_bounds__(256) attn_mma(const __half* __restrict__ qkv,
                                                __half* __restrict__ o) {
    extern __shared__ __half sm_h[];
    __half* sqk = sm_h;
    __half* svt = sm_h + 64 * SQK2;

    const int tid = threadIdx.x;
    const int n = blockIdx.x >> 1;
    const int hg = blockIdx.x & 1;
    const int cb = hg * 128;
    const long long gbase = (long long)n * 64 * 768;

#pragma unroll
    for (int i = 0; i < 8; i++) {
        const int s = tid + 256 * i;
        const int t = s >> 5;
        const int j = s & 31;
        const int srccol = cb + j * 8 + (j >= 16 ? 128 : 0);
        *(uint4*)&sqk[t * SQK2 + j * 8] = *(const uint4*)&qkv[gbase + t * 768 + srccol];
    }
#pragma unroll
    for (int i = 0; i < 16; i++) {
        const int p = tid + 256 * i;
        const int t = p >> 6;
        const int d0 = (p & 63) * 2;
        __half2 v = *(const __half2*)&qkv[gbase + t * 768 + 512 + cb + d0];
        const int hl = d0 >> 5, dh = d0 & 31;
        svt[hl * SVT2_H + dh * SVT2 + t] = __low2half(v);
        svt[hl * SVT2_H + (dh + 1) * SVT2 + t] = __high2half(v);
    }
    __syncthreads();

    const int w = tid >> 5, lane = tid & 31;
    const int hl = w >> 1, rh = w & 1;
    const int lm = lane >> 2, lk = lane & 3;

    const __half* qb = sqk + hl * 32 + 2 * lk;
    const __half* kb = sqk + 128 + hl * 32 + 2 * lk;

    float acc[2][8][4];
#pragma unroll
    for (int i = 0; i < 2; i++)
#pragma unroll
        for (int j = 0; j < 8; j++)
#pragma unroll
            for (int q = 0; q < 4; q++) acc[i][j][q] = 0.0f;

#pragma unroll
    for (int kt = 0; kt < 2; kt++) {
        uint32_t a[2][4];
#pragma unroll
        for (int mt = 0; mt < 2; mt++) {
            const int r0 = rh * 32 + mt * 16 + lm;
            const __half* q0 = qb + kt * 16;
            a[mt][0] = *(const uint32_t*)&q0[r0 * SQK2];
            a[mt][1] = *(const uint32_t*)&q0[(r0 + 8) * SQK2];
            a[mt][2] = *(const uint32_t*)&q0[r0 * SQK2 + 8];
            a[mt][3] = *(const uint32_t*)&q0[(r0 + 8) * SQK2 + 8];
        }
#pragma unroll
        for (int nt = 0; nt < 8; nt++) {
            const int kr = nt * 8 + lm;
            const __half* k0 = kb + kt * 16;
            uint32_t b0 = *(const uint32_t*)&k0[kr * SQK2];
            uint32_t b1 = *(const uint32_t*)&k0[kr * SQK2 + 8];
#pragma unroll
            for (int mt = 0; mt < 2; mt++)
                MMA_H(acc[mt][nt], a[mt][0], a[mt][1], a[mt][2], a[mt][3], b0, b1);
        }
    }

    const float cs = 0.17677669529663689f * 1.4426950408889634f;
    float rs[2][2];
#pragma unroll
    for (int mt = 0; mt < 2; mt++) {
        float m0 = -1e30f, m1 = -1e30f;
#pragma unroll
        for (int nt = 0; nt < 8; nt++) {
            m0 = fmaxf(m0, fmaxf(acc[mt][nt][0], acc[mt][nt][1]));
            m1 = fmaxf(m1, fmaxf(acc[mt][nt][2], acc[mt][nt][3]));
        }
        m0 = fmaxf(m0, __shfl_xor_sync(0xFFFFFFFFu, m0, 1));
        m0 = fmaxf(m0, __shfl_xor_sync(0xFFFFFFFFu, m0, 2));
        m1 = fmaxf(m1, __shfl_xor_sync(0xFFFFFFFFu, m1, 1));
        m1 = fmaxf(m1, __shfl_xor_sync(0xFFFFFFFFu, m1, 2));
        float s0 = 0.0f, s1 = 0.0f;
#pragma unroll
        for (int nt = 0; nt < 8; nt++) {
            float e0 = exp2f((acc[mt][nt][0] - m0) * cs);
            float e1 = exp2f((acc[mt][nt][1] - m0) * cs);
            float e2 = exp2f((acc[mt][nt][2] - m1) * cs);
            float e3 = exp2f((acc[mt][nt][3] - m1) * cs);
            acc[mt][nt][0] = e0; acc[mt][nt][1] = e1;
            acc[mt][nt][2] = e2; acc[mt][nt][3] = e3;
            s0 += e0 + e1; s1 += e2 + e3;
        }
        s0 += __shfl_xor_sync(0xFFFFFFFFu, s0, 1);
        s0 += __shfl_xor_sync(0xFFFFFFFFu, s0, 2);
        s1 += __shfl_xor_sync(0xFFFFFFFFu, s1, 1);
        s1 += __shfl_xor_sync(0xFFFFFFFFu, s1, 2);
        rs[mt][0] = 1.0f / s0;
        rs[mt][1] = 1.0f / s1;
    }

    float oacc[2][4][4];
#pragma unroll
    for (int i = 0; i < 2; i++)
#pragma unroll
        for (int j = 0; j < 4; j++)
#pragma unroll
            for (int q = 0; q < 4; q++) oacc[i][j][q] = 0.0f;

    const __half* vb0 = svt + hl * SVT2_H + 2 * lk;
#pragma unroll
    for (int kt4 = 0; kt4 < 4; kt4++) {
        uint32_t pa[2][4];
#pragma unroll
        for (int mt = 0; mt < 2; mt++) {
            pa[mt][0] = h2_u32(__floats2half2_rn(acc[mt][2 * kt4][0], acc[mt][2 * kt4][1]));
            pa[mt][1] = h2_u32(__floats2half2_rn(acc[mt][2 * kt4][2], acc[mt][2 * kt4][3]));
            pa[mt][2] = h2_u32(__floats2half2_rn(acc[mt][2 * kt4 + 1][0], acc[mt][2 * kt4 + 1][1]));
            pa[mt][3] = h2_u32(__floats2half2_rn(acc[mt][2 * kt4 + 1][2], acc[mt][2 * kt4 + 1][3]));
        }
#pragma unroll
        for (int dn = 0; dn < 4; dn++) {
            const __half* vb = vb0 + (dn * 8 + lm) * SVT2 + kt4 * 16;
            uint32_t b0 = *(const uint32_t*)&vb[0];
            uint32_t b1 = *(const uint32_t*)&vb[8];
#pragma unroll
            for (int mt = 0; mt < 2; mt++)
                MMA_H(oacc[mt][dn], pa[mt][0], pa[mt][1], pa[mt][2], pa[mt][3], b0, b1);
        }
    }

#pragma unroll
    for (int mt = 0; mt < 2; mt++) {
        const int r0 = rh * 32 + mt * 16 + lm;
#pragma unroll
        for (int dn = 0; dn < 4; dn++) {
            const int col = (hg * 4 + hl) * 32 + dn * 8 + 2 * lk;
            __half* o0 = o + ((long long)n * 64 + r0) * CDIM + col;
            __half* o1 = o + ((long long)n * 64 + r0 + 8) * CDIM + col;
            *(__half2*)o0 = __floats2half2_rn(oacc[mt][dn][0] * rs[mt][0],
                                              oacc[mt][dn][1] * rs[mt][0]);
            *(__half2*)o1 = __floats2half2_rn(oacc[mt][dn][2] * rs[mt][1],
                                              oacc[mt][dn][3] * rs[mt][1]);
        }
    }
}

// ===========================================================================
// Launch
// ===========================================================================
extern "C" void kernel_launch(void* const* d_in, const int* in_sizes, int n_in,
                              void* d_out, int out_size) {
    const float* x      = (const float*)d_in[0];
    const float* qkv_w  = (const float*)d_in[1];
    const float* qkv_b  = (const float*)d_in[2];
    const float* proj_w = (const float*)d_in[3];
    const float* proj_b = (const float*)d_in[4];
    const float* n1_g   = (const float*)d_in[5];
    const float* n1_b   = (const float*)d_in[6];
    const float* n2_g   = (const float*)d_in[7];
    const float* n2_b   = (const float*)d_in[8];
    const float* fc1_w  = (const float*)d_in[9];
    const float* fc1_b  = (const float*)d_in[10];
    const float* fc2_w  = (const float*)d_in[11];
    const float* fc2_b  = (const float*)d_in[12];
    float* out = (float*)d_out;

    float *tok;
    __half *yh, *qkvh, *oh, *wh;
    cudaGetSymbolAddress((void**)&tok, g_tok);
    cudaGetSymbolAddress((void**)&yh, g_yh);
    cudaGetSymbolAddress((void**)&qkvh, g_qkvh);
    cudaGetSymbolAddress((void**)&oh, g_oh);
    cudaGetSymbolAddress((void**)&wh, g_wh);

    cudaFuncSetAttribute(attn_mma, cudaFuncAttributeMaxDynamicSharedMemorySize, ATTN_SMEM);
    const int GLN_SMEM = 64 * 256 * 4;
    cudaFuncSetAttribute(gather_ln, cudaFuncAttributeMaxDynamicSharedMemorySize, GLN_SMEM);
    const int GEMM_SMEM = 98304;
    cudaFuncSetAttribute(mma_gemm_h<0>, cudaFuncAttributeMaxDynamicSharedMemorySize, GEMM_SMEM);
    cudaFuncSetAttribute(proj_ln, cudaFuncAttributeMaxDynamicSharedMemorySize, PROJ_SMEM);
    cudaFuncSetAttribute(mlp_fused, cudaFuncAttributeMaxDynamicSharedMemorySize, MLP_SMEM);

    const int MT = NTOK / 128;  // 2048 M-tiles

    // 0. weights -> fp16
    cvt_weights<<<512, 256>>>(qkv_w, proj_w, fc1_w, fc2_w);
    // 1+2. window partition + LN1 (fused)
    gather_ln<<<4096, 256, GLN_SMEM>>>(x, n1_g, n1_b, tok, yh);
    // 3. QKV gemm
    mma_gemm_h<0><<<dim3(6, MT), 256, GEMM_SMEM>>>(yh, wh + WOFF_QKV, qkv_b, qkvh, 768, 256);
    // 4. windowed attention (2 CTAs/window)
    attn_mma<<<8192, 256, ATTN_SMEM>>>(qkvh, oh);
    // 5+6. proj gemm + residual + LN2 (fused)
    proj_ln<<<MT, 512, PROJ_SMEM>>>(oh, wh + WOFF_PROJ, proj_b, tok, n2_g, n2_b, yh);
    // 7+8. fused MLP: fc1+GELU+fc2+residual+scatter -> out
    mlp_fused<<<MT, 512, MLP_SMEM>>>(yh, wh + WOFF_FC1, wh + WOFF_FC2,
                                     fc1_b, fc2_b, tok, out);
}

// round 16
// speedup vs baseline: 1.1627x; 1.1627x over previous
#include <cuda_runtime.h>
#include <cuda_fp16.h>
#include <math.h>
#include <cstdint>

// Problem constants
#define B_ 16
#define CDIM 256
#define H_ 128
#define W_ 128
#define NTOK 262144   // B*H*W tokens

// Scratch (device globals)
__device__ __half g_tokh[67108864];    // [NTOK, 256] fp16 residual stream
__device__ __half g_yh[67108864];      // [NTOK, 256] LN output fp16
__device__ __half g_qkvh[201326592];   // [NTOK, 768] fp16
__device__ __half g_oh[67108864];      // [NTOK, 256] fp16
__device__ __half g_hidh[268435456];   // [NTOK, 1024] fp16
__device__ __half g_wh[786432];        // qkv_w|proj_w|fc1_w|fc2_w fp16

#define WOFF_QKV 0
#define WOFF_PROJ 196608
#define WOFF_FC1 262144
#define WOFF_FC2 524288

__device__ __forceinline__ float gelu_exact(float v) {
    return 0.5f * v * (1.0f + erff(v * 0.70710678118654752f));
}

__device__ __forceinline__ uint32_t h2_u32(__half2 v) {
    return *reinterpret_cast<uint32_t*>(&v);
}

__device__ __forceinline__ void cpa16(uint32_t dst, const void* src) {
    asm volatile("cp.async.cg.shared.global [%0], [%1], 16;" :: "r"(dst), "l"(src));
}
#define CP_COMMIT() asm volatile("cp.async.commit_group;" ::: "memory")
#define CP_WAIT1()  asm volatile("cp.async.wait_group 1;" ::: "memory")

#define MMA_H(dd, a0, a1, a2, a3, b0, b1) \
    asm volatile( \
        "mma.sync.aligned.m16n8k16.row.col.f32.f16.f16.f32 " \
        "{%0,%1,%2,%3}, {%4,%5,%6,%7}, {%8,%9}, {%0,%1,%2,%3};" \
        : "+f"((dd)[0]), "+f"((dd)[1]), "+f"((dd)[2]), "+f"((dd)[3]) \
        : "r"(a0), "r"(a1), "r"(a2), "r"(a3), "r"(b0), "r"(b1))

#define LDSM_X4(r0, r1, r2, r3, addr) \
    asm volatile("ldmatrix.sync.aligned.m8n8.x4.shared.b16 {%0,%1,%2,%3}, [%4];" \
        : "=r"(r0), "=r"(r1), "=r"(r2), "=r"(r3) : "r"(addr))

// ===========================================================================
// Weight conversion fp32 -> fp16
// ===========================================================================
__global__ void __launch_bounds__(256) cvt_weights(const float* __restrict__ qkv_w,
                                                   const float* __restrict__ proj_w,
                                                   const float* __restrict__ fc1_w,
                                                   const float* __restrict__ fc2_w) {
    for (int i = blockIdx.x * 256 + threadIdx.x; i < 786432; i += gridDim.x * 256) {
        float v;
        if (i < WOFF_PROJ)      v = qkv_w[i - WOFF_QKV];
        else if (i < WOFF_FC1)  v = proj_w[i - WOFF_PROJ];
        else if (i < WOFF_FC2)  v = fc1_w[i - WOFF_FC1];
        else                    v = fc2_w[i - WOFF_FC2];
        g_wh[i] = __float2half_rn(v);
    }
}

// ===========================================================================
// FP16 mma.sync GEMM, ldmatrix fragment loads (R14 structure).
// EPI: 0=bias->f16, 2=bias+GELU->f16, 3=bias+residual(fp16)->scatter NCHW fp32
// ===========================================================================
template <int EPI>
__global__ void __launch_bounds__(256, 2) mma_gemm_h(const __half* __restrict__ A,
                                                     const __half* __restrict__ Wm,
                                                     const float* __restrict__ bias,
                                                     const __half* __restrict__ R,
                                                     void* __restrict__ OutV,
                                                     int N, int K) {
    extern __shared__ uint32_t sm[];
    uint32_t* As = sm;
    uint32_t* Bs = sm + 12288;

    const int tid = threadIdx.x;
    const int wid = tid >> 5;
    const int lane = tid & 31;
    const long long m0 = (long long)blockIdx.y * 128;
    const int n0 = blockIdx.x * 128;

    const int wm = (wid >> 2) * 64;
    const int wn = (wid & 3) * 32;
    const int lm = lane >> 2;
    const int lk = lane & 3;

    const uint32_t as_b = (uint32_t)__cvta_generic_to_shared(As);
    const uint32_t bs_b = (uint32_t)__cvta_generic_to_shared(Bs);

    uint32_t soff[4];
    const __half* aptr[4];
    const __half* bptr[4];
#pragma unroll
    for (int j = 0; j < 4; j++) {
        const int id = tid + 256 * j;
        const int row = id >> 3;
        const int seg = id & 7;
        soff[j] = (uint32_t)(row * 32 + ((seg * 4) ^ ((row & 7) * 4))) * 4u;
        aptr[j] = A + (m0 + row) * (long long)K + seg * 8;
        bptr[j] = Wm + (long long)(n0 + row) * K + seg * 8;
    }

    const int KT = K >> 6;

#pragma unroll
    for (int s = 0; s < 2; s++) {
        const uint32_t sb = s * 16384u;
#pragma unroll
        for (int j = 0; j < 4; j++) {
            cpa16(as_b + sb + soff[j], aptr[j] + s * 64);
            cpa16(bs_b + sb + soff[j], bptr[j] + s * 64);
        }
        CP_COMMIT();
    }

    const int l8 = lane & 7;
    const int subm = (lane >> 3) & 1;
    const int subk = lane >> 4;
    uint32_t aRowOff[4], aSwz[4];
#pragma unroll
    for (int mf = 0; mf < 4; mf++) {
        const int rowA = wm + mf * 16 + subm * 8 + l8;
        aRowOff[mf] = (uint32_t)rowA * 32;
        aSwz[mf] = (uint32_t)(rowA & 7) * 4;
    }
    uint32_t bRowOff[2], bSwz[2];
#pragma unroll
    for (int p = 0; p < 2; p++) {
        const int rowB = wn + p * 16 + subk * 8 + l8;
        bRowOff[p] = (uint32_t)rowB * 32;
        bSwz[p] = (uint32_t)(rowB & 7) * 4;
    }

    float d[4][4][4];
#pragma unroll
    for (int i = 0; i < 4; i++)
#pragma unroll
        for (int j = 0; j < 4; j++)
#pragma unroll
            for (int q = 0; q < 4; q++) d[i][j][q] = 0.0f;

    int stage = 0;
    for (int kt = 0; kt < KT; kt++) {
        CP_WAIT1();
        __syncthreads();

        if (kt + 2 < KT) {
            const int s2 = stage + 2 >= 3 ? stage - 1 : stage + 2;
            const int ko = (kt + 2) * 64;
            const uint32_t sb = s2 * 16384u;
#pragma unroll
            for (int j = 0; j < 4; j++) {
                cpa16(as_b + sb + soff[j], aptr[j] + ko);
                cpa16(bs_b + sb + soff[j], bptr[j] + ko);
            }
        }
        CP_COMMIT();

        const uint32_t aBase = as_b + stage * 16384u;
        const uint32_t bBase = bs_b + stage * 16384u;
#pragma unroll
        for (int ks = 0; ks < 4; ks++) {
            const uint32_t kcA = (uint32_t)(ks * 8 + subk * 4);
            const uint32_t kcB = (uint32_t)(ks * 8 + subm * 4);
            uint32_t a[4][4];
#pragma unroll
            for (int mf = 0; mf < 4; mf++) {
                const uint32_t addr = aBase + (aRowOff[mf] + (kcA ^ aSwz[mf])) * 4u;
                LDSM_X4(a[mf][0], a[mf][1], a[mf][2], a[mf][3], addr);
            }
            uint32_t b[4][2];
#pragma unroll
            for (int p = 0; p < 2; p++) {
                const uint32_t addr = bBase + (bRowOff[p] + (kcB ^ bSwz[p])) * 4u;
                LDSM_X4(b[2 * p][0], b[2 * p][1], b[2 * p + 1][0], b[2 * p + 1][1], addr);
            }
#pragma unroll
            for (int mf = 0; mf < 4; mf++)
#pragma unroll
                for (int nf = 0; nf < 4; nf++)
                    MMA_H(d[mf][nf], a[mf][0], a[mf][1], a[mf][2], a[mf][3],
                          b[nf][0], b[nf][1]);
        }
        stage = stage + 1 >= 3 ? 0 : stage + 1;
    }

#pragma unroll
    for (int nf = 0; nf < 4; nf++) {
        const int gcol = n0 + wn + nf * 8 + 2 * lk;
        const float2 bv = *(const float2*)&bias[gcol];
#pragma unroll
        for (int mf = 0; mf < 4; mf++) {
            const long long row = m0 + wm + mf * 16 + lm;
            float2 v0, v1;
            v0.x = d[mf][nf][0] + bv.x;
            v0.y = d[mf][nf][1] + bv.y;
            v1.x = d[mf][nf][2] + bv.x;
            v1.y = d[mf][nf][3] + bv.y;
            if (EPI == 3) {
                float2 r0 = __half22float2(*(const __half2*)&R[row * (long long)N + gcol]);
                float2 r1 = __half22float2(*(const __half2*)&R[(row + 8) * (long long)N + gcol]);
                v0.x += r0.x; v0.y += r0.y;
                v1.x += r1.x; v1.y += r1.y;
                const int n_ = (int)(row >> 6);
                const int t_ = (int)(row & 63);
                const int bb = n_ >> 8, wy = (n_ >> 4) & 15, wx = n_ & 15;
                const int hh = wy * 8 + (t_ >> 3), ww = wx * 8 + (t_ & 7);
                float* Out = (float*)OutV;
                const long long base0 =
                    ((long long)(bb * 256 + gcol) << 14) + hh * 128 + ww;
                Out[base0] = v0.x;
                Out[base0 + 16384] = v0.y;
                Out[base0 + 128] = v1.x;
                Out[base0 + 16384 + 128] = v1.y;
            } else {
                if (EPI == 2) {
                    v0.x = gelu_exact(v0.x); v0.y = gelu_exact(v0.y);
                    v1.x = gelu_exact(v1.x); v1.y = gelu_exact(v1.y);
                }
                __half* Out = (__half*)OutV;
                *(__half2*)&Out[row * (long long)N + gcol] = __floats2half2_rn(v0.x, v0.y);
                *(__half2*)&Out[(row + 8) * (long long)N + gcol] = __floats2half2_rn(v1.x, v1.y);
            }
        }
    }
}

// ===========================================================================
// Fused proj GEMM + residual(fp16) + LN2 (R14 structure, tok fp16)
// ===========================================================================
#define PROJ_SMEM (147456 + 4096 + 1024)

__global__ void __launch_bounds__(512) proj_ln(const __half* __restrict__ A,
                                               const __half* __restrict__ Wm,
                                               const float* __restrict__ bias,
                                               __half* __restrict__ tok,
                                               const float* __restrict__ g2,
                                               const float* __restrict__ b2,
                                               __half* __restrict__ yh) {
    extern __shared__ uint32_t sm[];
    uint32_t* As = sm;
    uint32_t* Bs = sm + 12288;
    float* spart = (float*)(sm + 36864);
    float* smr   = spart + 1024;

    const int tid = threadIdx.x;
    const int wid = tid >> 5;
    const int lane = tid & 31;
    const long long m0 = (long long)blockIdx.x * 128;

    const int wr = wid >> 2;
    const int wc = wid & 3;
    const int lm = lane >> 2;
    const int lk = lane & 3;

    const uint32_t as_b = (uint32_t)__cvta_generic_to_shared(As);
    const uint32_t bs_b = (uint32_t)__cvta_generic_to_shared(Bs);

    uint32_t aoff[2];
    const __half* aptr[2];
#pragma unroll
    for (int j = 0; j < 2; j++) {
        const int id = tid + 512 * j;
        const int row = id >> 3;
        const int seg = id & 7;
        aoff[j] = (uint32_t)(row * 32 + ((seg * 4) ^ ((row & 7) * 4))) * 4u;
        aptr[j] = A + (m0 + row) * 256LL + seg * 8;
    }
    uint32_t boff[4];
    const __half* bptr[4];
#pragma unroll
    for (int j = 0; j < 4; j++) {
        const int id = tid + 512 * j;
        const int row = id >> 3;
        const int seg = id & 7;
        boff[j] = (uint32_t)(row * 32 + ((seg * 4) ^ ((row & 7) * 4))) * 4u;
        bptr[j] = Wm + (long long)row * 256 + seg * 8;
    }

#pragma unroll
    for (int s = 0; s < 2; s++) {
        const uint32_t sbA = s * 16384u;
        const uint32_t sbB = s * 32768u;
#pragma unroll
        for (int j = 0; j < 2; j++) cpa16(as_b + sbA + aoff[j], aptr[j] + s * 64);
#pragma unroll
        for (int j = 0; j < 4; j++) cpa16(bs_b + sbB + boff[j], bptr[j] + s * 64);
        CP_COMMIT();
    }

    const int l8 = lane & 7;
    const int subm = (lane >> 3) & 1;
    const int subk = lane >> 4;
    uint32_t aRowOff[2], aSwz[2];
#pragma unroll
    for (int mf = 0; mf < 2; mf++) {
        const int rowA = wr * 32 + mf * 16 + subm * 8 + l8;
        aRowOff[mf] = (uint32_t)rowA * 32;
        aSwz[mf] = (uint32_t)(rowA & 7) * 4;
    }
    uint32_t bRowOff[4], bSwz[4];
#pragma unroll
    for (int p = 0; p < 4; p++) {
        const int rowB = wc * 64 + p * 16 + subk * 8 + l8;
        bRowOff[p] = (uint32_t)rowB * 32;
        bSwz[p] = (uint32_t)(rowB & 7) * 4;
    }

    float d[2][8][4];
#pragma unroll
    for (int i = 0; i < 2; i++)
#pragma unroll
        for (int j = 0; j < 8; j++)
#pragma unroll
            for (int q = 0; q < 4; q++) d[i][j][q] = 0.0f;

    int stage = 0;
    for (int kt = 0; kt < 4; kt++) {
        CP_WAIT1();
        __syncthreads();

        if (kt + 2 < 4) {
            const int s2 = stage + 2 >= 3 ? stage - 1 : stage + 2;
            const int ko = (kt + 2) * 64;
            const uint32_t sbA = s2 * 16384u;
            const uint32_t sbB = s2 * 32768u;
#pragma unroll
            for (int j = 0; j < 2; j++) cpa16(as_b + sbA + aoff[j], aptr[j] + ko);
#pragma unroll
            for (int j = 0; j < 4; j++) cpa16(bs_b + sbB + boff[j], bptr[j] + ko);
        }
        CP_COMMIT();

        const uint32_t aBase = as_b + stage * 16384u;
        const uint32_t bBase = bs_b + stage * 32768u;
#pragma unroll
        for (int ks = 0; ks < 4; ks++) {
            const uint32_t kcA = (uint32_t)(ks * 8 + subk * 4);
            const uint32_t kcB = (uint32_t)(ks * 8 + subm * 4);
            uint32_t a[2][4];
#pragma unroll
            for (int mf = 0; mf < 2; mf++) {
                const uint32_t addr = aBase + (aRowOff[mf] + (kcA ^ aSwz[mf])) * 4u;
                LDSM_X4(a[mf][0], a[mf][1], a[mf][2], a[mf][3], addr);
            }
            uint32_t b[8][2];
#pragma unroll
            for (int p = 0; p < 4; p++) {
                const uint32_t addr = bBase + (bRowOff[p] + (kcB ^ bSwz[p])) * 4u;
                LDSM_X4(b[2 * p][0], b[2 * p][1], b[2 * p + 1][0], b[2 * p + 1][1], addr);
            }
#pragma unroll
            for (int mf = 0; mf < 2; mf++)
#pragma unroll
                for (int nf = 0; nf < 8; nf++)
                    MMA_H(d[mf][nf], a[mf][0], a[mf][1], a[mf][2], a[mf][3],
                          b[nf][0], b[nf][1]);
        }
        stage = stage + 1 >= 3 ? 0 : stage + 1;
    }

    float rsum[2][2], rsq[2][2];
#pragma unroll
    for (int i = 0; i < 2; i++) { rsum[i][0] = rsum[i][1] = 0.0f; rsq[i][0] = rsq[i][1] = 0.0f; }

#pragma unroll
    for (int nf = 0; nf < 8; nf++) {
        const int gcol = wc * 64 + nf * 8 + 2 * lk;
        const float2 bv = *(const float2*)&bias[gcol];
#pragma unroll
        for (int mf = 0; mf < 2; mf++) {
            const long long r0 = m0 + wr * 32 + mf * 16 + lm;
            float2 q0 = __half22float2(*(const __half2*)&tok[r0 * 256 + gcol]);
            float2 q1 = __half22float2(*(const __half2*)&tok[(r0 + 8) * 256 + gcol]);
            float2 v0, v1;
            v0.x = d[mf][nf][0] + bv.x + q0.x;
            v0.y = d[mf][nf][1] + bv.y + q0.y;
            v1.x = d[mf][nf][2] + bv.x + q1.x;
            v1.y = d[mf][nf][3] + bv.y + q1.y;
            d[mf][nf][0] = v0.x; d[mf][nf][1] = v0.y;
            d[mf][nf][2] = v1.x; d[mf][nf][3] = v1.y;
            *(__half2*)&tok[r0 * 256 + gcol] = __floats2half2_rn(v0.x, v0.y);
            *(__half2*)&tok[(r0 + 8) * 256 + gcol] = __floats2half2_rn(v1.x, v1.y);
            rsum[mf][0] += v0.x + v0.y;  rsq[mf][0] += v0.x * v0.x + v0.y * v0.y;
            rsum[mf][1] += v1.x + v1.y;  rsq[mf][1] += v1.x * v1.x + v1.y * v1.y;
        }
    }
#pragma unroll
    for (int mf = 0; mf < 2; mf++)
#pragma unroll
        for (int s = 0; s < 2; s++) {
            rsum[mf][s] += __shfl_xor_sync(0xFFFFFFFFu, rsum[mf][s], 1);
            rsum[mf][s] += __shfl_xor_sync(0xFFFFFFFFu, rsum[mf][s], 2);
            rsq[mf][s]  += __shfl_xor_sync(0xFFFFFFFFu, rsq[mf][s], 1);
            rsq[mf][s]  += __shfl_xor_sync(0xFFFFFFFFu, rsq[mf][s], 2);
        }
    if (lk == 0) {
#pragma unroll
        for (int mf = 0; mf < 2; mf++)
#pragma unroll
            for (int s = 0; s < 2; s++) {
                const int r = wr * 32 + mf * 16 + s * 8 + lm;
                spart[(r * 4 + wc) * 2] = rsum[mf][s];
                spart[(r * 4 + wc) * 2 + 1] = rsq[mf][s];
            }
    }
    __syncthreads();
    if (tid < 128) {
        float s = 0.0f, q = 0.0f;
#pragma unroll
        for (int c = 0; c < 4; c++) {
            s += spart[(tid * 4 + c) * 2];
            q += spart[(tid * 4 + c) * 2 + 1];
        }
        const float mu = s * (1.0f / 256.0f);
        const float var = q * (1.0f / 256.0f) - mu * mu;
        smr[tid * 2] = mu;
        smr[tid * 2 + 1] = rsqrtf(var + 1e-5f);
    }
    __syncthreads();

#pragma unroll
    for (int nf = 0; nf < 8; nf++) {
        const int gcol = wc * 64 + nf * 8 + 2 * lk;
        const float2 gv = *(const float2*)&g2[gcol];
        const float2 bv = *(const float2*)&b2[gcol];
#pragma unroll
        for (int mf = 0; mf < 2; mf++) {
            const int rl0 = wr * 32 + mf * 16 + lm;
            const float mu0 = smr[rl0 * 2],       ri0 = smr[rl0 * 2 + 1];
            const float mu1 = smr[(rl0 + 8) * 2], ri1 = smr[(rl0 + 8) * 2 + 1];
            const long long r0 = m0 + rl0;
            __half2 h0 = __floats2half2_rn((d[mf][nf][0] - mu0) * ri0 * gv.x + bv.x,
                                           (d[mf][nf][1] - mu0) * ri0 * gv.y + bv.y);
            __half2 h1 = __floats2half2_rn((d[mf][nf][2] - mu1) * ri1 * gv.x + bv.x,
                                           (d[mf][nf][3] - mu1) * ri1 * gv.y + bv.y);
            *(__half2*)&yh[r0 * 256 + gcol] = h0;
            *(__half2*)&yh[(r0 + 8) * 256 + gcol] = h1;
        }
    }
}

// ===========================================================================
// Fused gather + LN1 (tok now fp16)
// ===========================================================================
__global__ void __launch_bounds__(256) gather_ln(const float* __restrict__ x,
                                                 const float* __restrict__ g,
                                                 const float* __restrict__ b,
                                                 __half* __restrict__ tok,
                                                 __half* __restrict__ yh) {
    extern __shared__ float st[];

    const int tid = threadIdx.x;
    const int n = blockIdx.x;
    const int bb = n >> 8, wy = (n >> 4) & 15, wx = n & 15;

#pragma unroll
    for (int j = 0; j < 8; j++) {
        const int p = tid + 256 * j;
        const int c = p >> 3;
        const int iy = p & 7;
        const float* xp = x + (((long long)(bb * 256 + c)) << 14)
                        + (wy * 8 + iy) * 128 + wx * 8;
        float4 u0 = *(const float4*)xp;
        float4 u1 = *(const float4*)(xp + 4);
        const int cs = c ^ (iy * 4);
        float* row0 = st + (iy * 8) * 256;
        row0[0 * 256 + cs] = u0.x;
        row0[1 * 256 + cs] = u0.y;
        row0[2 * 256 + cs] = u0.z;
        row0[3 * 256 + cs] = u0.w;
        row0[4 * 256 + cs] = u1.x;
        row0[5 * 256 + cs] = u1.y;
        row0[6 * 256 + cs] = u1.z;
        row0[7 * 256 + cs] = u1.w;
    }
    __syncthreads();

    const int w = tid >> 5, lane = tid & 31;
#pragma unroll
    for (int r = 0; r < 8; r++) {
        const int t = w * 8 + r;
        const int xr = ((t >> 3) & 7) * 4;
        const float* row = st + t * 256;
        float4 v0 = *(const float4*)&row[(4 * lane) ^ xr];
        float4 v1 = *(const float4*)&row[(128 + 4 * lane) ^ xr];

        float s = v0.x + v0.y + v0.z + v0.w + v1.x + v1.y + v1.z + v1.w;
#pragma unroll
        for (int o = 16; o; o >>= 1) s += __shfl_xor_sync(0xFFFFFFFFu, s, o);
        const float mu = s * (1.0f / 256.0f);

        float q = (v0.x - mu) * (v0.x - mu) + (v0.y - mu) * (v0.y - mu)
                + (v0.z - mu) * (v0.z - mu) + (v0.w - mu) * (v0.w - mu)
                + (v1.x - mu) * (v1.x - mu) + (v1.y - mu) * (v1.y - mu)
                + (v1.z - mu) * (v1.z - mu) + (v1.w - mu) * (v1.w - mu);
#pragma unroll
        for (int o = 16; o; o >>= 1) q += __shfl_xor_sync(0xFFFFFFFFu, q, o);
        const float rinv = rsqrtf(q * (1.0f / 256.0f) + 1e-5f);

        const long long grow = (long long)n * 64 + t;
        __half* trow = tok + grow * CDIM;
        *(__half2*)&trow[4 * lane]       = __floats2half2_rn(v0.x, v0.y);
        *(__half2*)&trow[4 * lane + 2]   = __floats2half2_rn(v0.z, v0.w);
        *(__half2*)&trow[128 + 4 * lane]     = __floats2half2_rn(v1.x, v1.y);
        *(__half2*)&trow[128 + 4 * lane + 2] = __floats2half2_rn(v1.z, v1.w);

        float4 g0 = *(const float4*)&g[4 * lane];
        float4 g1 = *(const float4*)&g[128 + 4 * lane];
        float4 b0 = *(const float4*)&b[4 * lane];
        float4 b1 = *(const float4*)&b[128 + 4 * lane];
        __half* yrow = yh + grow * CDIM;
        *(__half2*)&yrow[4 * lane] = __floats2half2_rn((v0.x - mu) * rinv * g0.x + b0.x,
                                                       (v0.y - mu) * rinv * g0.y + b0.y);
        *(__half2*)&yrow[4 * lane + 2] = __floats2half2_rn((v0.z - mu) * rinv * g0.z + b0.z,
                                                           (v0.w - mu) * rinv * g0.w + b0.w);
        *(__half2*)&yrow[128 + 4 * lane] = __floats2half2_rn((v1.x - mu) * rinv * g1.x + b1.x,
                                                             (v1.y - mu) * rinv * g1.y + b1.y);
        *(__half2*)&yrow[128 + 4 * lane + 2] = __floats2half2_rn((v1.z - mu) * rinv * g1.z + b1.z,
                                                                 (v1.w - mu) * rinv * g1.w + b1.w);
    }
}

// ===========================================================================
// Tensor-core window attention (unchanged from R14 fixed version)
// ===========================================================================
#define SQK2 264
#define SVT2 70
#define SVT2_H 2240
#define ATTN_SMEM ((64 * SQK2 + 4 * SVT2_H) * 2)

__global__ void __launch_bounds__(256) attn_mma(const __half* __restrict__ qkv,
                                                __half* __restrict__ o) {
    extern __shared__ __half sm_h[];
    __half* sqk = sm_h;
    __half* svt = sm_h + 64 * SQK2;

    const int tid = threadIdx.x;
    const int n = blockIdx.x >> 1;
    const int hg = blockIdx.x & 1;
    const int cb = hg * 128;
    const long long gbase = (long long)n * 64 * 768;

#pragma unroll
    for (int i = 0; i < 8; i++) {
        const int s = tid + 256 * i;
        const int t = s >> 5;
        const int j = s & 31;
        const int srccol = cb + j * 8 + (j >= 16 ? 128 : 0);
        *(uint4*)&sqk[t * SQK2 + j * 8] = *(const uint4*)&qkv[gbase + t * 768 + srccol];
    }
#pragma unroll
    for (int i = 0; i < 16; i++) {
        const int p = tid + 256 * i;
        const int t = p >> 6;
        const int d0 = (p & 63) * 2;
        __half2 v = *(const __half2*)&qkv[gbase + t * 768 + 512 + cb + d0];
        const int hl = d0 >> 5, dh = d0 & 31;
        svt[hl * SVT2_H + dh * SVT2 + t] = __low2half(v);
        svt[hl * SVT2_H + (dh + 1) * SVT2 + t] = __high2half(v);
    }
    __syncthreads();

    const int w = tid >> 5, lane = tid & 31;
    const int hl = w >> 1, rh = w & 1;
    const int lm = lane >> 2, lk = lane & 3;

    const __half* qb = sqk + hl * 32 + 2 * lk;
    const __half* kb = sqk + 128 + hl * 32 + 2 * lk;

    float acc[2][8][4];
#pragma unroll
    for (int i = 0; i < 2; i++)
#pragma unroll
        for (int j = 0; j < 8; j++)
#pragma unroll
            for (int q = 0; q < 4; q++) acc[i][j][q] = 0.0f;

#pragma unroll
    for (int kt = 0; kt < 2; kt++) {
        uint32_t a[2][4];
#pragma unroll
        for (int mt = 0; mt < 2; mt++) {
            const int r0 = rh * 32 + mt * 16 + lm;
            const __half* q0 = qb + kt * 16;
            a[mt][0] = *(const uint32_t*)&q0[r0 * SQK2];
            a[mt][1] = *(const uint32_t*)&q0[(r0 + 8) * SQK2];
            a[mt][2] = *(const uint32_t*)&q0[r0 * SQK2 + 8];
            a[mt][3] = *(const uint32_t*)&q0[(r0 + 8) * SQK2 + 8];
        }
#pragma unroll
        for (int nt = 0; nt < 8; nt++) {
            const int kr = nt * 8 + lm;
            const __half* k0 = kb + kt * 16;
            uint32_t b0 = *(const uint32_t*)&k0[kr * SQK2];
            uint32_t b1 = *(const uint32_t*)&k0[kr * SQK2 + 8];
#pragma unroll
            for (int mt = 0; mt < 2; mt++)
                MMA_H(acc[mt][nt], a[mt][0], a[mt][1], a[mt][2], a[mt][3], b0, b1);
        }
    }

    const float cs = 0.17677669529663689f * 1.4426950408889634f;
    float rs[2][2];
#pragma unroll
    for (int mt = 0; mt < 2; mt++) {
        float m0 = -1e30f, m1 = -1e30f;
#pragma unroll
        for (int nt = 0; nt < 8; nt++) {
            m0 = fmaxf(m0, fmaxf(acc[mt][nt][0], acc[mt][nt][1]));
            m1 = fmaxf(m1, fmaxf(acc[mt][nt][2], acc[mt][nt][3]));
        }
        m0 = fmaxf(m0, __shfl_xor_sync(0xFFFFFFFFu, m0, 1));
        m0 = fmaxf(m0, __shfl_xor_sync(0xFFFFFFFFu, m0, 2));
        m1 = fmaxf(m1, __shfl_xor_sync(0xFFFFFFFFu, m1, 1));
        m1 = fmaxf(m1, __shfl_xor_sync(0xFFFFFFFFu, m1, 2));
        float s0 = 0.0f, s1 = 0.0f;
#pragma unroll
        for (int nt = 0; nt < 8; nt++) {
            float e0 = exp2f((acc[mt][nt][0] - m0) * cs);
            float e1 = exp2f((acc[mt][nt][1] - m0) * cs);
            float e2 = exp2f((acc[mt][nt][2] - m1) * cs);
            float e3 = exp2f((acc[mt][nt][3] - m1) * cs);
            acc[mt][nt][0] = e0; acc[mt][nt][1] = e1;
            acc[mt][nt][2] = e2; acc[mt][nt][3] = e3;
            s0 += e0 + e1; s1 += e2 + e3;
        }
        s0 += __shfl_xor_sync(0xFFFFFFFFu, s0, 1);
        s0 += __shfl_xor_sync(0xFFFFFFFFu, s0, 2);
        s1 += __shfl_xor_sync(0xFFFFFFFFu, s1, 1);
        s1 += __shfl_xor_sync(0xFFFFFFFFu, s1, 2);
        rs[mt][0] = 1.0f / s0;
        rs[mt][1] = 1.0f / s1;
    }

    float oacc[2][4][4];
#pragma unroll
    for (int i = 0; i < 2; i++)
#pragma unroll
        for (int j = 0; j < 4; j++)
#pragma unroll
            for (int q = 0; q < 4; q++) oacc[i][j][q] = 0.0f;

    const __half* vb0 = svt + hl * SVT2_H + 2 * lk;
#pragma unroll
    for (int kt4 = 0; kt4 < 4; kt4++) {
        uint32_t pa[2][4];
#pragma unroll
        for (int mt = 0; mt < 2; mt++) {
            pa[mt][0] = h2_u32(__floats2half2_rn(acc[mt][2 * kt4][0], acc[mt][2 * kt4][1]));
            pa[mt][1] = h2_u32(__floats2half2_rn(acc[mt][2 * kt4][2], acc[mt][2 * kt4][3]));
            pa[mt][2] = h2_u32(__floats2half2_rn(acc[mt][2 * kt4 + 1][0], acc[mt][2 * kt4 + 1][1]));
            pa[mt][3] = h2_u32(__floats2half2_rn(acc[mt][2 * kt4 + 1][2], acc[mt][2 * kt4 + 1][3]));
        }
#pragma unroll
        for (int dn = 0; dn < 4; dn++) {
            const __half* vb = vb0 + (dn * 8 + lm) * SVT2 + kt4 * 16;
            uint32_t b0 = *(const uint32_t*)&vb[0];
            uint32_t b1 = *(const uint32_t*)&vb[8];
#pragma unroll
            for (int mt = 0; mt < 2; mt++)
                MMA_H(oacc[mt][dn], pa[mt][0], pa[mt][1], pa[mt][2], pa[mt][3], b0, b1);
        }
    }

#pragma unroll
    for (int mt = 0; mt < 2; mt++) {
        const int r0 = rh * 32 + mt * 16 + lm;
#pragma unroll
        for (int dn = 0; dn < 4; dn++) {
            const int col = (hg * 4 + hl) * 32 + dn * 8 + 2 * lk;
            __half* o0 = o + ((long long)n * 64 + r0) * CDIM + col;
            __half* o1 = o + ((long long)n * 64 + r0 + 8) * CDIM + col;
            *(__half2*)o0 = __floats2half2_rn(oacc[mt][dn][0] * rs[mt][0],
                                              oacc[mt][dn][1] * rs[mt][0]);
            *(__half2*)o1 = __floats2half2_rn(oacc[mt][dn][2] * rs[mt][1],
                                              oacc[mt][dn][3] * rs[mt][1]);
        }
    }
}

// ===========================================================================
// Launch
// ===========================================================================
extern "C" void kernel_launch(void* const* d_in, const int* in_sizes, int n_in,
                              void* d_out, int out_size) {
    const float* x      = (const float*)d_in[0];
    const float* qkv_w  = (const float*)d_in[1];
    const float* qkv_b  = (const float*)d_in[2];
    const float* proj_w = (const float*)d_in[3];
    const float* proj_b = (const float*)d_in[4];
    const float* n1_g   = (const float*)d_in[5];
    const float* n1_b   = (const float*)d_in[6];
    const float* n2_g   = (const float*)d_in[7];
    const float* n2_b   = (const float*)d_in[8];
    const float* fc1_w  = (const float*)d_in[9];
    const float* fc1_b  = (const float*)d_in[10];
    const float* fc2_w  = (const float*)d_in[11];
    const float* fc2_b  = (const float*)d_in[12];
    float* out = (float*)d_out;

    __half *tokh, *yh, *qkvh, *oh, *hidh, *wh;
    cudaGetSymbolAddress((void**)&tokh, g_tokh);
    cudaGetSymbolAddress((void**)&yh, g_yh);
    cudaGetSymbolAddress((void**)&qkvh, g_qkvh);
    cudaGetSymbolAddress((void**)&oh, g_oh);
    cudaGetSymbolAddress((void**)&hidh, g_hidh);
    cudaGetSymbolAddress((void**)&wh, g_wh);

    cudaFuncSetAttribute(attn_mma, cudaFuncAttributeMaxDynamicSharedMemorySize, ATTN_SMEM);
    const int GLN_SMEM = 64 * 256 * 4;
    cudaFuncSetAttribute(gather_ln, cudaFuncAttributeMaxDynamicSharedMemorySize, GLN_SMEM);
    const int GEMM_SMEM = 98304;
    cudaFuncSetAttribute(mma_gemm_h<0>, cudaFuncAttributeMaxDynamicSharedMemorySize, GEMM_SMEM);
    cudaFuncSetAttribute(mma_gemm_h<2>, cudaFuncAttributeMaxDynamicSharedMemorySize, GEMM_SMEM);
    cudaFuncSetAttribute(mma_gemm_h<3>, cudaFuncAttributeMaxDynamicSharedMemorySize, GEMM_SMEM);
    cudaFuncSetAttribute(proj_ln, cudaFuncAttributeMaxDynamicSharedMemorySize, PROJ_SMEM);

    const int MT = NTOK / 128;  // 2048 M-tiles

    // 0. weights -> fp16
    cvt_weights<<<512, 256>>>(qkv_w, proj_w, fc1_w, fc2_w);
    // 1+2. window partition + LN1 (fused); residual stream fp16
    gather_ln<<<4096, 256, GLN_SMEM>>>(x, n1_g, n1_b, tokh, yh);
    // 3. QKV gemm
    mma_gemm_h<0><<<dim3(6, MT), 256, GEMM_SMEM>>>(yh, wh + WOFF_QKV, qkv_b, nullptr, qkvh, 768, 256);
    // 4. windowed attention (2 CTAs/window)
    attn_mma<<<8192, 256, ATTN_SMEM>>>(qkvh, oh);
    // 5+6. proj gemm + residual + LN2 (fused)
    proj_ln<<<MT, 512, PROJ_SMEM>>>(oh, wh + WOFF_PROJ, proj_b, tokh, n2_g, n2_b, yh);
    // 7. fc1 gemm + GELU
    mma_gemm_h<2><<<dim3(8, MT), 256, GEMM_SMEM>>>(yh, wh + WOFF_FC1, fc1_b, nullptr, hidh, 1024, 256);
    // 8. fc2 gemm + residual + scatter -> out
    mma_gemm_h<3><<<dim3(2, MT), 256, GEMM_SMEM>>>(hidh, wh + WOFF_FC2, fc2_b, tokh, out, 256, 1024);
}

// round 17
// speedup vs baseline: 1.1724x; 1.0083x over previous
#include <cuda_runtime.h>
#include <cuda_fp16.h>
#include <math.h>
#include <cstdint>

// Problem constants
#define B_ 16
#define CDIM 256
#define H_ 128
#define W_ 128
#define NTOK 262144   // B*H*W tokens

// Scratch (device globals)
__device__ __half g_tokh[67108864];    // [NTOK, 256] fp16 residual stream
__device__ __half g_yh[67108864];      // [NTOK, 256] LN output fp16
__device__ __half g_qkvh[201326592];   // [NTOK, 768] fp16
__device__ __half g_oh[67108864];      // [NTOK, 256] fp16
__device__ __half g_hidh[268435456];   // [NTOK, 1024] fp16
__device__ __half g_wh[786432];        // qkv_w|proj_w|fc1_w|fc2_w fp16

#define WOFF_QKV 0
#define WOFF_PROJ 196608
#define WOFF_FC1 262144
#define WOFF_FC2 524288

__device__ __forceinline__ float gelu_exact(float v) {
    return 0.5f * v * (1.0f + erff(v * 0.70710678118654752f));
}

__device__ __forceinline__ uint32_t h2_u32(__half2 v) {
    return *reinterpret_cast<uint32_t*>(&v);
}

__device__ __forceinline__ void cpa16(uint32_t dst, const void* src) {
    asm volatile("cp.async.cg.shared.global [%0], [%1], 16;" :: "r"(dst), "l"(src));
}
#define CP_COMMIT() asm volatile("cp.async.commit_group;" ::: "memory")
#define CP_WAIT1()  asm volatile("cp.async.wait_group 1;" ::: "memory")

#define MMA_H(dd, a0, a1, a2, a3, b0, b1) \
    asm volatile( \
        "mma.sync.aligned.m16n8k16.row.col.f32.f16.f16.f32 " \
        "{%0,%1,%2,%3}, {%4,%5,%6,%7}, {%8,%9}, {%0,%1,%2,%3};" \
        : "+f"((dd)[0]), "+f"((dd)[1]), "+f"((dd)[2]), "+f"((dd)[3]) \
        : "r"(a0), "r"(a1), "r"(a2), "r"(a3), "r"(b0), "r"(b1))

#define LDSM_X4(r0, r1, r2, r3, addr) \
    asm volatile("ldmatrix.sync.aligned.m8n8.x4.shared.b16 {%0,%1,%2,%3}, [%4];" \
        : "=r"(r0), "=r"(r1), "=r"(r2), "=r"(r3) : "r"(addr))

#define LDSM_X4T(r0, r1, r2, r3, addr) \
    asm volatile("ldmatrix.sync.aligned.m8n8.x4.trans.shared.b16 {%0,%1,%2,%3}, [%4];" \
        : "=r"(r0), "=r"(r1), "=r"(r2), "=r"(r3) : "r"(addr))

// ===========================================================================
// Weight conversion fp32 -> fp16
// ===========================================================================
__global__ void __launch_bounds__(256) cvt_weights(const float* __restrict__ qkv_w,
                                                   const float* __restrict__ proj_w,
                                                   const float* __restrict__ fc1_w,
                                                   const float* __restrict__ fc2_w) {
    for (int i = blockIdx.x * 256 + threadIdx.x; i < 786432; i += gridDim.x * 256) {
        float v;
        if (i < WOFF_PROJ)      v = qkv_w[i - WOFF_QKV];
        else if (i < WOFF_FC1)  v = proj_w[i - WOFF_PROJ];
        else if (i < WOFF_FC2)  v = fc1_w[i - WOFF_FC1];
        else                    v = fc2_w[i - WOFF_FC2];
        g_wh[i] = __float2half_rn(v);
    }
}

// ===========================================================================
// FP16 mma.sync GEMM (unchanged from R16).
// EPI: 0=bias->f16, 2=bias+GELU->f16, 3=bias+residual(fp16)->scatter NCHW fp32
// ===========================================================================
template <int EPI>
__global__ void __launch_bounds__(256, 2) mma_gemm_h(const __half* __restrict__ A,
                                                     const __half* __restrict__ Wm,
                                                     const float* __restrict__ bias,
                                                     const __half* __restrict__ R,
                                                     void* __restrict__ OutV,
                                                     int N, int K) {
    extern __shared__ uint32_t sm[];
    uint32_t* As = sm;
    uint32_t* Bs = sm + 12288;

    const int tid = threadIdx.x;
    const int wid = tid >> 5;
    const int lane = tid & 31;
    const long long m0 = (long long)blockIdx.y * 128;
    const int n0 = blockIdx.x * 128;

    const int wm = (wid >> 2) * 64;
    const int wn = (wid & 3) * 32;
    const int lm = lane >> 2;
    const int lk = lane & 3;

    const uint32_t as_b = (uint32_t)__cvta_generic_to_shared(As);
    const uint32_t bs_b = (uint32_t)__cvta_generic_to_shared(Bs);

    uint32_t soff[4];
    const __half* aptr[4];
    const __half* bptr[4];
#pragma unroll
    for (int j = 0; j < 4; j++) {
        const int id = tid + 256 * j;
        const int row = id >> 3;
        const int seg = id & 7;
        soff[j] = (uint32_t)(row * 32 + ((seg * 4) ^ ((row & 7) * 4))) * 4u;
        aptr[j] = A + (m0 + row) * (long long)K + seg * 8;
        bptr[j] = Wm + (long long)(n0 + row) * K + seg * 8;
    }

    const int KT = K >> 6;

#pragma unroll
    for (int s = 0; s < 2; s++) {
        const uint32_t sb = s * 16384u;
#pragma unroll
        for (int j = 0; j < 4; j++) {
            cpa16(as_b + sb + soff[j], aptr[j] + s * 64);
            cpa16(bs_b + sb + soff[j], bptr[j] + s * 64);
        }
        CP_COMMIT();
    }

    const int l8 = lane & 7;
    const int subm = (lane >> 3) & 1;
    const int subk = lane >> 4;
    uint32_t aRowOff[4], aSwz[4];
#pragma unroll
    for (int mf = 0; mf < 4; mf++) {
        const int rowA = wm + mf * 16 + subm * 8 + l8;
        aRowOff[mf] = (uint32_t)rowA * 32;
        aSwz[mf] = (uint32_t)(rowA & 7) * 4;
    }
    uint32_t bRowOff[2], bSwz[2];
#pragma unroll
    for (int p = 0; p < 2; p++) {
        const int rowB = wn + p * 16 + subk * 8 + l8;
        bRowOff[p] = (uint32_t)rowB * 32;
        bSwz[p] = (uint32_t)(rowB & 7) * 4;
    }

    float d[4][4][4];
#pragma unroll
    for (int i = 0; i < 4; i++)
#pragma unroll
        for (int j = 0; j < 4; j++)
#pragma unroll
            for (int q = 0; q < 4; q++) d[i][j][q] = 0.0f;

    int stage = 0;
    for (int kt = 0; kt < KT; kt++) {
        CP_WAIT1();
        __syncthreads();

        if (kt + 2 < KT) {
            const int s2 = stage + 2 >= 3 ? stage - 1 : stage + 2;
            const int ko = (kt + 2) * 64;
            const uint32_t sb = s2 * 16384u;
#pragma unroll
            for (int j = 0; j < 4; j++) {
                cpa16(as_b + sb + soff[j], aptr[j] + ko);
                cpa16(bs_b + sb + soff[j], bptr[j] + ko);
            }
        }
        CP_COMMIT();

        const uint32_t aBase = as_b + stage * 16384u;
        const uint32_t bBase = bs_b + stage * 16384u;
#pragma unroll
        for (int ks = 0; ks < 4; ks++) {
            const uint32_t kcA = (uint32_t)(ks * 8 + subk * 4);
            const uint32_t kcB = (uint32_t)(ks * 8 + subm * 4);
            uint32_t a[4][4];
#pragma unroll
            for (int mf = 0; mf < 4; mf++) {
                const uint32_t addr = aBase + (aRowOff[mf] + (kcA ^ aSwz[mf])) * 4u;
                LDSM_X4(a[mf][0], a[mf][1], a[mf][2], a[mf][3], addr);
            }
            uint32_t b[4][2];
#pragma unroll
            for (int p = 0; p < 2; p++) {
                const uint32_t addr = bBase + (bRowOff[p] + (kcB ^ bSwz[p])) * 4u;
                LDSM_X4(b[2 * p][0], b[2 * p][1], b[2 * p + 1][0], b[2 * p + 1][1], addr);
            }
#pragma unroll
            for (int mf = 0; mf < 4; mf++)
#pragma unroll
                for (int nf = 0; nf < 4; nf++)
                    MMA_H(d[mf][nf], a[mf][0], a[mf][1], a[mf][2], a[mf][3],
                          b[nf][0], b[nf][1]);
        }
        stage = stage + 1 >= 3 ? 0 : stage + 1;
    }

#pragma unroll
    for (int nf = 0; nf < 4; nf++) {
        const int gcol = n0 + wn + nf * 8 + 2 * lk;
        const float2 bv = *(const float2*)&bias[gcol];
#pragma unroll
        for (int mf = 0; mf < 4; mf++) {
            const long long row = m0 + wm + mf * 16 + lm;
            float2 v0, v1;
            v0.x = d[mf][nf][0] + bv.x;
            v0.y = d[mf][nf][1] + bv.y;
            v1.x = d[mf][nf][2] + bv.x;
            v1.y = d[mf][nf][3] + bv.y;
            if (EPI == 3) {
                float2 r0 = __half22float2(*(const __half2*)&R[row * (long long)N + gcol]);
                float2 r1 = __half22float2(*(const __half2*)&R[(row + 8) * (long long)N + gcol]);
                v0.x += r0.x; v0.y += r0.y;
                v1.x += r1.x; v1.y += r1.y;
                const int n_ = (int)(row >> 6);
                const int t_ = (int)(row & 63);
                const int bb = n_ >> 8, wy = (n_ >> 4) & 15, wx = n_ & 15;
                const int hh = wy * 8 + (t_ >> 3), ww = wx * 8 + (t_ & 7);
                float* Out = (float*)OutV;
                const long long base0 =
                    ((long long)(bb * 256 + gcol) << 14) + hh * 128 + ww;
                Out[base0] = v0.x;
                Out[base0 + 16384] = v0.y;
                Out[base0 + 128] = v1.x;
                Out[base0 + 16384 + 128] = v1.y;
            } else {
                if (EPI == 2) {
                    v0.x = gelu_exact(v0.x); v0.y = gelu_exact(v0.y);
                    v1.x = gelu_exact(v1.x); v1.y = gelu_exact(v1.y);
                }
                __half* Out = (__half*)OutV;
                *(__half2*)&Out[row * (long long)N + gcol] = __floats2half2_rn(v0.x, v0.y);
                *(__half2*)&Out[(row + 8) * (long long)N + gcol] = __floats2half2_rn(v1.x, v1.y);
            }
        }
    }
}

// ===========================================================================
// Fused proj GEMM + residual(fp16) + LN2 (unchanged from R16)
// ===========================================================================
#define PROJ_SMEM (147456 + 4096 + 1024)

__global__ void __launch_bounds__(512) proj_ln(const __half* __restrict__ A,
                                               const __half* __restrict__ Wm,
                                               const float* __restrict__ bias,
                                               __half* __restrict__ tok,
                                               const float* __restrict__ g2,
                                               const float* __restrict__ b2,
                                               __half* __restrict__ yh) {
    extern __shared__ uint32_t sm[];
    uint32_t* As = sm;
    uint32_t* Bs = sm + 12288;
    float* spart = (float*)(sm + 36864);
    float* smr   = spart + 1024;

    const int tid = threadIdx.x;
    const int wid = tid >> 5;
    const int lane = tid & 31;
    const long long m0 = (long long)blockIdx.x * 128;

    const int wr = wid >> 2;
    const int wc = wid & 3;
    const int lm = lane >> 2;
    const int lk = lane & 3;

    const uint32_t as_b = (uint32_t)__cvta_generic_to_shared(As);
    const uint32_t bs_b = (uint32_t)__cvta_generic_to_shared(Bs);

    uint32_t aoff[2];
    const __half* aptr[2];
#pragma unroll
    for (int j = 0; j < 2; j++) {
        const int id = tid + 512 * j;
        const int row = id >> 3;
        const int seg = id & 7;
        aoff[j] = (uint32_t)(row * 32 + ((seg * 4) ^ ((row & 7) * 4))) * 4u;
        aptr[j] = A + (m0 + row) * 256LL + seg * 8;
    }
    uint32_t boff[4];
    const __half* bptr[4];
#pragma unroll
    for (int j = 0; j < 4; j++) {
        const int id = tid + 512 * j;
        const int row = id >> 3;
        const int seg = id & 7;
        boff[j] = (uint32_t)(row * 32 + ((seg * 4) ^ ((row & 7) * 4))) * 4u;
        bptr[j] = Wm + (long long)row * 256 + seg * 8;
    }

#pragma unroll
    for (int s = 0; s < 2; s++) {
        const uint32_t sbA = s * 16384u;
        const uint32_t sbB = s * 32768u;
#pragma unroll
        for (int j = 0; j < 2; j++) cpa16(as_b + sbA + aoff[j], aptr[j] + s * 64);
#pragma unroll
        for (int j = 0; j < 4; j++) cpa16(bs_b + sbB + boff[j], bptr[j] + s * 64);
        CP_COMMIT();
    }

    const int l8 = lane & 7;
    const int subm = (lane >> 3) & 1;
    const int subk = lane >> 4;
    uint32_t aRowOff[2], aSwz[2];
#pragma unroll
    for (int mf = 0; mf < 2; mf++) {
        const int rowA = wr * 32 + mf * 16 + subm * 8 + l8;
        aRowOff[mf] = (uint32_t)rowA * 32;
        aSwz[mf] = (uint32_t)(rowA & 7) * 4;
    }
    uint32_t bRowOff[4], bSwz[4];
#pragma unroll
    for (int p = 0; p < 4; p++) {
        const int rowB = wc * 64 + p * 16 + subk * 8 + l8;
        bRowOff[p] = (uint32_t)rowB * 32;
        bSwz[p] = (uint32_t)(rowB & 7) * 4;
    }

    float d[2][8][4];
#pragma unroll
    for (int i = 0; i < 2; i++)
#pragma unroll
        for (int j = 0; j < 8; j++)
#pragma unroll
            for (int q = 0; q < 4; q++) d[i][j][q] = 0.0f;

    int stage = 0;
    for (int kt = 0; kt < 4; kt++) {
        CP_WAIT1();
        __syncthreads();

        if (kt + 2 < 4) {
            const int s2 = stage + 2 >= 3 ? stage - 1 : stage + 2;
            const int ko = (kt + 2) * 64;
            const uint32_t sbA = s2 * 16384u;
            const uint32_t sbB = s2 * 32768u;
#pragma unroll
            for (int j = 0; j < 2; j++) cpa16(as_b + sbA + aoff[j], aptr[j] + ko);
#pragma unroll
            for (int j = 0; j < 4; j++) cpa16(bs_b + sbB + boff[j], bptr[j] + ko);
        }
        CP_COMMIT();

        const uint32_t aBase = as_b + stage * 16384u;
        const uint32_t bBase = bs_b + stage * 32768u;
#pragma unroll
        for (int ks = 0; ks < 4; ks++) {
            const uint32_t kcA = (uint32_t)(ks * 8 + subk * 4);
            const uint32_t kcB = (uint32_t)(ks * 8 + subm * 4);
            uint32_t a[2][4];
#pragma unroll
            for (int mf = 0; mf < 2; mf++) {
                const uint32_t addr = aBase + (aRowOff[mf] + (kcA ^ aSwz[mf])) * 4u;
                LDSM_X4(a[mf][0], a[mf][1], a[mf][2], a[mf][3], addr);
            }
            uint32_t b[8][2];
#pragma unroll
            for (int p = 0; p < 4; p++) {
                const uint32_t addr = bBase + (bRowOff[p] + (kcB ^ bSwz[p])) * 4u;
                LDSM_X4(b[2 * p][0], b[2 * p][1], b[2 * p + 1][0], b[2 * p + 1][1], addr);
            }
#pragma unroll
            for (int mf = 0; mf < 2; mf++)
#pragma unroll
                for (int nf = 0; nf < 8; nf++)
                    MMA_H(d[mf][nf], a[mf][0], a[mf][1], a[mf][2], a[mf][3],
                          b[nf][0], b[nf][1]);
        }
        stage = stage + 1 >= 3 ? 0 : stage + 1;
    }

    float rsum[2][2], rsq[2][2];
#pragma unroll
    for (int i = 0; i < 2; i++) { rsum[i][0] = rsum[i][1] = 0.0f; rsq[i][0] = rsq[i][1] = 0.0f; }

#pragma unroll
    for (int nf = 0; nf < 8; nf++) {
        const int gcol = wc * 64 + nf * 8 + 2 * lk;
        const float2 bv = *(const float2*)&bias[gcol];
#pragma unroll
        for (int mf = 0; mf < 2; mf++) {
            const long long r0 = m0 + wr * 32 + mf * 16 + lm;
            float2 q0 = __half22float2(*(const __half2*)&tok[r0 * 256 + gcol]);
            float2 q1 = __half22float2(*(const __half2*)&tok[(r0 + 8) * 256 + gcol]);
            float2 v0, v1;
            v0.x = d[mf][nf][0] + bv.x + q0.x;
            v0.y = d[mf][nf][1] + bv.y + q0.y;
            v1.x = d[mf][nf][2] + bv.x + q1.x;
            v1.y = d[mf][nf][3] + bv.y + q1.y;
            d[mf][nf][0] = v0.x; d[mf][nf][1] = v0.y;
            d[mf][nf][2] = v1.x; d[mf][nf][3] = v1.y;
            *(__half2*)&tok[r0 * 256 + gcol] = __floats2half2_rn(v0.x, v0.y);
            *(__half2*)&tok[(r0 + 8) * 256 + gcol] = __floats2half2_rn(v1.x, v1.y);
            rsum[mf][0] += v0.x + v0.y;  rsq[mf][0] += v0.x * v0.x + v0.y * v0.y;
            rsum[mf][1] += v1.x + v1.y;  rsq[mf][1] += v1.x * v1.x + v1.y * v1.y;
        }
    }
#pragma unroll
    for (int mf = 0; mf < 2; mf++)
#pragma unroll
        for (int s = 0; s < 2; s++) {
            rsum[mf][s] += __shfl_xor_sync(0xFFFFFFFFu, rsum[mf][s], 1);
            rsum[mf][s] += __shfl_xor_sync(0xFFFFFFFFu, rsum[mf][s], 2);
            rsq[mf][s]  += __shfl_xor_sync(0xFFFFFFFFu, rsq[mf][s], 1);
            rsq[mf][s]  += __shfl_xor_sync(0xFFFFFFFFu, rsq[mf][s], 2);
        }
    if (lk == 0) {
#pragma unroll
        for (int mf = 0; mf < 2; mf++)
#pragma unroll
            for (int s = 0; s < 2; s++) {
                const int r = wr * 32 + mf * 16 + s * 8 + lm;
                spart[(r * 4 + wc) * 2] = rsum[mf][s];
                spart[(r * 4 + wc) * 2 + 1] = rsq[mf][s];
            }
    }
    __syncthreads();
    if (tid < 128) {
        float s = 0.0f, q = 0.0f;
#pragma unroll
        for (int c = 0; c < 4; c++) {
            s += spart[(tid * 4 + c) * 2];
            q += spart[(tid * 4 + c) * 2 + 1];
        }
        const float mu = s * (1.0f / 256.0f);
        const float var = q * (1.0f / 256.0f) - mu * mu;
        smr[tid * 2] = mu;
        smr[tid * 2 + 1] = rsqrtf(var + 1e-5f);
    }
    __syncthreads();

#pragma unroll
    for (int nf = 0; nf < 8; nf++) {
        const int gcol = wc * 64 + nf * 8 + 2 * lk;
        const float2 gv = *(const float2*)&g2[gcol];
        const float2 bv = *(const float2*)&b2[gcol];
#pragma unroll
        for (int mf = 0; mf < 2; mf++) {
            const int rl0 = wr * 32 + mf * 16 + lm;
            const float mu0 = smr[rl0 * 2],       ri0 = smr[rl0 * 2 + 1];
            const float mu1 = smr[(rl0 + 8) * 2], ri1 = smr[(rl0 + 8) * 2 + 1];
            const long long r0 = m0 + rl0;
            __half2 h0 = __floats2half2_rn((d[mf][nf][0] - mu0) * ri0 * gv.x + bv.x,
                                           (d[mf][nf][1] - mu0) * ri0 * gv.y + bv.y);
            __half2 h1 = __floats2half2_rn((d[mf][nf][2] - mu1) * ri1 * gv.x + bv.x,
                                           (d[mf][nf][3] - mu1) * ri1 * gv.y + bv.y);
            *(__half2*)&yh[r0 * 256 + gcol] = h0;
            *(__half2*)&yh[(r0 + 8) * 256 + gcol] = h1;
        }
    }
}

// ===========================================================================
// Fused gather + LN1 (unchanged from R16)
// ===========================================================================
__global__ void __launch_bounds__(256) gather_ln(const float* __restrict__ x,
                                                 const float* __restrict__ g,
                                                 const float* __restrict__ b,
                                                 __half* __restrict__ tok,
                                                 __half* __restrict__ yh) {
    extern __shared__ float st[];

    const int tid = threadIdx.x;
    const int n = blockIdx.x;
    const int bb = n >> 8, wy = (n >> 4) & 15, wx = n & 15;

#pragma unroll
    for (int j = 0; j < 8; j++) {
        const int p = tid + 256 * j;
        const int c = p >> 3;
        const int iy = p & 7;
        const float* xp = x + (((long long)(bb * 256 + c)) << 14)
                        + (wy * 8 + iy) * 128 + wx * 8;
        float4 u0 = *(const float4*)xp;
        float4 u1 = *(const float4*)(xp + 4);
        const int cs = c ^ (iy * 4);
        float* row0 = st + (iy * 8) * 256;
        row0[0 * 256 + cs] = u0.x;
        row0[1 * 256 + cs] = u0.y;
        row0[2 * 256 + cs] = u0.z;
        row0[3 * 256 + cs] = u0.w;
        row0[4 * 256 + cs] = u1.x;
        row0[5 * 256 + cs] = u1.y;
        row0[6 * 256 + cs] = u1.z;
        row0[7 * 256 + cs] = u1.w;
    }
    __syncthreads();

    const int w = tid >> 5, lane = tid & 31;
#pragma unroll
    for (int r = 0; r < 8; r++) {
        const int t = w * 8 + r;
        const int xr = ((t >> 3) & 7) * 4;
        const float* row = st + t * 256;
        float4 v0 = *(const float4*)&row[(4 * lane) ^ xr];
        float4 v1 = *(const float4*)&row[(128 + 4 * lane) ^ xr];

        float s = v0.x + v0.y + v0.z + v0.w + v1.x + v1.y + v1.z + v1.w;
#pragma unroll
        for (int o = 16; o; o >>= 1) s += __shfl_xor_sync(0xFFFFFFFFu, s, o);
        const float mu = s * (1.0f / 256.0f);

        float q = (v0.x - mu) * (v0.x - mu) + (v0.y - mu) * (v0.y - mu)
                + (v0.z - mu) * (v0.z - mu) + (v0.w - mu) * (v0.w - mu)
                + (v1.x - mu) * (v1.x - mu) + (v1.y - mu) * (v1.y - mu)
                + (v1.z - mu) * (v1.z - mu) + (v1.w - mu) * (v1.w - mu);
#pragma unroll
        for (int o = 16; o; o >>= 1) q += __shfl_xor_sync(0xFFFFFFFFu, q, o);
        const float rinv = rsqrtf(q * (1.0f / 256.0f) + 1e-5f);

        const long long grow = (long long)n * 64 + t;
        __half* trow = tok + grow * CDIM;
        *(__half2*)&trow[4 * lane]       = __floats2half2_rn(v0.x, v0.y);
        *(__half2*)&trow[4 * lane + 2]   = __floats2half2_rn(v0.z, v0.w);
        *(__half2*)&trow[128 + 4 * lane]     = __floats2half2_rn(v1.x, v1.y);
        *(__half2*)&trow[128 + 4 * lane + 2] = __floats2half2_rn(v1.z, v1.w);

        float4 g0 = *(const float4*)&g[4 * lane];
        float4 g1 = *(const float4*)&g[128 + 4 * lane];
        float4 b0 = *(const float4*)&b[4 * lane];
        float4 b1 = *(const float4*)&b[128 + 4 * lane];
        __half* yrow = yh + grow * CDIM;
        *(__half2*)&yrow[4 * lane] = __floats2half2_rn((v0.x - mu) * rinv * g0.x + b0.x,
                                                       (v0.y - mu) * rinv * g0.y + b0.y);
        *(__half2*)&yrow[4 * lane + 2] = __floats2half2_rn((v0.z - mu) * rinv * g0.z + b0.z,
                                                           (v0.w - mu) * rinv * g0.w + b0.w);
        *(__half2*)&yrow[128 + 4 * lane] = __floats2half2_rn((v1.x - mu) * rinv * g1.x + b1.x,
                                                             (v1.y - mu) * rinv * g1.y + b1.y);
        *(__half2*)&yrow[128 + 4 * lane + 2] = __floats2half2_rn((v1.z - mu) * rinv * g1.z + b1.z,
                                                                 (v1.w - mu) * rinv * g1.w + b1.w);
    }
}

// ===========================================================================
// Tensor-core window attention, ldmatrix fragment loads.
// 2 CTAs per window (4 heads each), 256 thr.
// sqk [64][264]: q (0..127) | k (128..255). sv [64][136]: V natural layout.
// QK A/B via ldmatrix.x4; PV B via ldmatrix.x4.trans (V^T on the fly).
// ===========================================================================
#define SQKH 264
#define SVH 136
#define ATTN_SMEM ((64 * SQKH + 64 * SVH) * 2)

__global__ void __launch_bounds__(256) attn_mma(const __half* __restrict__ qkv,
                                                __half* __restrict__ o) {
    extern __shared__ __half sm_h[];
    __half* sqk = sm_h;                   // [64][264]
    __half* sv  = sm_h + 64 * SQKH;       // [64][136]

    const int tid = threadIdx.x;
    const int n = blockIdx.x >> 1;
    const int hg = blockIdx.x & 1;
    const int cb = hg * 128;
    const long long gbase = (long long)n * 64 * 768;

    // stage q,k: 2048 uint4
#pragma unroll
    for (int i = 0; i < 8; i++) {
        const int s = tid + 256 * i;
        const int t = s >> 5;
        const int j = s & 31;
        const int srccol = cb + j * 8 + (j >= 16 ? 128 : 0);
        *(uint4*)&sqk[t * SQKH + j * 8] = *(const uint4*)&qkv[gbase + t * 768 + srccol];
    }
    // stage v natural: 1024 uint4
#pragma unroll
    for (int i = 0; i < 4; i++) {
        const int p = tid + 256 * i;
        const int t = p >> 4;
        const int seg = p & 15;
        *(uint4*)&sv[t * SVH + seg * 8] = *(const uint4*)&qkv[gbase + t * 768 + 512 + cb + seg * 8];
    }
    __syncthreads();

    const int w = tid >> 5, lane = tid & 31;
    const int hl = w >> 1, rh = w & 1;
    const int lm = lane >> 2, lk = lane & 3;
    const int l8 = lane & 7;
    const int subm = (lane >> 3) & 1;
    const int subk = lane >> 4;

    const uint32_t sqkb = (uint32_t)__cvta_generic_to_shared(sqk);
    const uint32_t svb  = (uint32_t)__cvta_generic_to_shared(sv);

    float acc[2][8][4];
#pragma unroll
    for (int i = 0; i < 2; i++)
#pragma unroll
        for (int j = 0; j < 8; j++)
#pragma unroll
            for (int q = 0; q < 4; q++) acc[i][j][q] = 0.0f;

    // ---- QK^T via ldmatrix ----
#pragma unroll
    for (int kt = 0; kt < 2; kt++) {
        uint32_t a[2][4];
#pragma unroll
        for (int mt = 0; mt < 2; mt++) {
            const int row = rh * 32 + mt * 16 + subm * 8 + l8;
            const uint32_t addr = sqkb + (uint32_t)(row * SQKH + hl * 32 + kt * 16 + subk * 8) * 2u;
            LDSM_X4(a[mt][0], a[mt][1], a[mt][2], a[mt][3], addr);
        }
        uint32_t b[8][2];
#pragma unroll
        for (int p = 0; p < 4; p++) {
            const int row = p * 16 + subk * 8 + l8;
            const uint32_t addr = sqkb + (uint32_t)(row * SQKH + 128 + hl * 32 + kt * 16 + subm * 8) * 2u;
            LDSM_X4(b[2 * p][0], b[2 * p][1], b[2 * p + 1][0], b[2 * p + 1][1], addr);
        }
#pragma unroll
        for (int mt = 0; mt < 2; mt++)
#pragma unroll
            for (int nt = 0; nt < 8; nt++)
                MMA_H(acc[mt][nt], a[mt][0], a[mt][1], a[mt][2], a[mt][3],
                      b[nt][0], b[nt][1]);
    }

    // ---- softmax (registers) ----
    const float cs = 0.17677669529663689f * 1.4426950408889634f;
    float rs[2][2];
#pragma unroll
    for (int mt = 0; mt < 2; mt++) {
        float m0 = -1e30f, m1 = -1e30f;
#pragma unroll
        for (int nt = 0; nt < 8; nt++) {
            m0 = fmaxf(m0, fmaxf(acc[mt][nt][0], acc[mt][nt][1]));
            m1 = fmaxf(m1, fmaxf(acc[mt][nt][2], acc[mt][nt][3]));
        }
        m0 = fmaxf(m0, __shfl_xor_sync(0xFFFFFFFFu, m0, 1));
        m0 = fmaxf(m0, __shfl_xor_sync(0xFFFFFFFFu, m0, 2));
        m1 = fmaxf(m1, __shfl_xor_sync(0xFFFFFFFFu, m1, 1));
        m1 = fmaxf(m1, __shfl_xor_sync(0xFFFFFFFFu, m1, 2));
        float s0 = 0.0f, s1 = 0.0f;
#pragma unroll
        for (int nt = 0; nt < 8; nt++) {
            float e0 = exp2f((acc[mt][nt][0] - m0) * cs);
            float e1 = exp2f((acc[mt][nt][1] - m0) * cs);
            float e2 = exp2f((acc[mt][nt][2] - m1) * cs);
            float e3 = exp2f((acc[mt][nt][3] - m1) * cs);
            acc[mt][nt][0] = e0; acc[mt][nt][1] = e1;
            acc[mt][nt][2] = e2; acc[mt][nt][3] = e3;
            s0 += e0 + e1; s1 += e2 + e3;
        }
        s0 += __shfl_xor_sync(0xFFFFFFFFu, s0, 1);
        s0 += __shfl_xor_sync(0xFFFFFFFFu, s0, 2);
        s1 += __shfl_xor_sync(0xFFFFFFFFu, s1, 1);
        s1 += __shfl_xor_sync(0xFFFFFFFFu, s1, 2);
        rs[mt][0] = 1.0f / s0;
        rs[mt][1] = 1.0f / s1;
    }

    // ---- PV: B fragments from natural V via ldmatrix.trans ----
    float oacc[2][4][4];
#pragma unroll
    for (int i = 0; i < 2; i++)
#pragma unroll
        for (int j = 0; j < 4; j++)
#pragma unroll
            for (int q = 0; q < 4; q++) oacc[i][j][q] = 0.0f;

#pragma unroll
    for (int kt4 = 0; kt4 < 4; kt4++) {
        uint32_t pa[2][4];
#pragma unroll
        for (int mt = 0; mt < 2; mt++) {
            pa[mt][0] = h2_u32(__floats2half2_rn(acc[mt][2 * kt4][0], acc[mt][2 * kt4][1]));
            pa[mt][1] = h2_u32(__floats2half2_rn(acc[mt][2 * kt4][2], acc[mt][2 * kt4][3]));
            pa[mt][2] = h2_u32(__floats2half2_rn(acc[mt][2 * kt4 + 1][0], acc[mt][2 * kt4 + 1][1]));
            pa[mt][3] = h2_u32(__floats2half2_rn(acc[mt][2 * kt4 + 1][2], acc[mt][2 * kt4 + 1][3]));
        }
        uint32_t b[4][2];
#pragma unroll
        for (int dp = 0; dp < 2; dp++) {
            const int rowk = kt4 * 16 + subm * 8 + l8;       // token (k)
            const int coln = hl * 32 + dp * 16 + subk * 8;   // head dim (n)
            const uint32_t addr = svb + (uint32_t)(rowk * SVH + coln) * 2u;
            LDSM_X4T(b[2 * dp][0], b[2 * dp][1], b[2 * dp + 1][0], b[2 * dp + 1][1], addr);
        }
#pragma unroll
        for (int dn = 0; dn < 4; dn++)
#pragma unroll
            for (int mt = 0; mt < 2; mt++)
                MMA_H(oacc[mt][dn], pa[mt][0], pa[mt][1], pa[mt][2], pa[mt][3],
                      b[dn][0], b[dn][1]);
    }

    // ---- epilogue: normalize, fp16, write ----
#pragma unroll
    for (int mt = 0; mt < 2; mt++) {
        const int r0 = rh * 32 + mt * 16 + lm;
#pragma unroll
        for (int dn = 0; dn < 4; dn++) {
            const int col = (hg * 4 + hl) * 32 + dn * 8 + 2 * lk;
            __half* o0 = o + ((long long)n * 64 + r0) * CDIM + col;
            __half* o1 = o + ((long long)n * 64 + r0 + 8) * CDIM + col;
            *(__half2*)o0 = __floats2half2_rn(oacc[mt][dn][0] * rs[mt][0],
                                              oacc[mt][dn][1] * rs[mt][0]);
            *(__half2*)o1 = __floats2half2_rn(oacc[mt][dn][2] * rs[mt][1],
                                              oacc[mt][dn][3] * rs[mt][1]);
        }
    }
}

// ===========================================================================
// Launch
// ===========================================================================
extern "C" void kernel_launch(void* const* d_in, const int* in_sizes, int n_in,
                              void* d_out, int out_size) {
    const float* x      = (const float*)d_in[0];
    const float* qkv_w  = (const float*)d_in[1];
    const float* qkv_b  = (const float*)d_in[2];
    const float* proj_w = (const float*)d_in[3];
    const float* proj_b = (const float*)d_in[4];
    const float* n1_g   = (const float*)d_in[5];
    const float* n1_b   = (const float*)d_in[6];
    const float* n2_g   = (const float*)d_in[7];
    const float* n2_b   = (const float*)d_in[8];
    const float* fc1_w  = (const float*)d_in[9];
    const float* fc1_b  = (const float*)d_in[10];
    const float* fc2_w  = (const float*)d_in[11];
    const float* fc2_b  = (const float*)d_in[12];
    float* out = (float*)d_out;

    __half *tokh, *yh, *qkvh, *oh, *hidh, *wh;
    cudaGetSymbolAddress((void**)&tokh, g_tokh);
    cudaGetSymbolAddress((void**)&yh, g_yh);
    cudaGetSymbolAddress((void**)&qkvh, g_qkvh);
    cudaGetSymbolAddress((void**)&oh, g_oh);
    cudaGetSymbolAddress((void**)&hidh, g_hidh);
    cudaGetSymbolAddress((void**)&wh, g_wh);

    cudaFuncSetAttribute(attn_mma, cudaFuncAttributeMaxDynamicSharedMemorySize, ATTN_SMEM);
    const int GLN_SMEM = 64 * 256 * 4;
    cudaFuncSetAttribute(gather_ln, cudaFuncAttributeMaxDynamicSharedMemorySize, GLN_SMEM);
    const int GEMM_SMEM = 98304;
    cudaFuncSetAttribute(mma_gemm_h<0>, cudaFuncAttributeMaxDynamicSharedMemorySize, GEMM_SMEM);
    cudaFuncSetAttribute(mma_gemm_h<2>, cudaFuncAttributeMaxDynamicSharedMemorySize, GEMM_SMEM);
    cudaFuncSetAttribute(mma_gemm_h<3>, cudaFuncAttributeMaxDynamicSharedMemorySize, GEMM_SMEM);
    cudaFuncSetAttribute(proj_ln, cudaFuncAttributeMaxDynamicSharedMemorySize, PROJ_SMEM);

    const int MT = NTOK / 128;  // 2048 M-tiles

    // 0. weights -> fp16
    cvt_weights<<<512, 256>>>(qkv_w, proj_w, fc1_w, fc2_w);
    // 1+2. window partition + LN1 (fused); residual stream fp16
    gather_ln<<<4096, 256, GLN_SMEM>>>(x, n1_g, n1_b, tokh, yh);
    // 3. QKV gemm
    mma_gemm_h<0><<<dim3(6, MT), 256, GEMM_SMEM>>>(yh, wh + WOFF_QKV, qkv_b, nullptr, qkvh, 768, 256);
    // 4. windowed attention (2 CTAs/window, ldmatrix)
    attn_mma<<<8192, 256, ATTN_SMEM>>>(qkvh, oh);
    // 5+6. proj gemm + residual + LN2 (fused)
    proj_ln<<<MT, 512, PROJ_SMEM>>>(oh, wh + WOFF_PROJ, proj_b, tokh, n2_g, n2_b, yh);
    // 7. fc1 gemm + GELU
    mma_gemm_h<2><<<dim3(8, MT), 256, GEMM_SMEM>>>(yh, wh + WOFF_FC1, fc1_b, nullptr, hidh, 1024, 256);
    // 8. fc2 gemm + residual + scatter -> out
    mma_gemm_h<3><<<dim3(2, MT), 256, GEMM_SMEM>>>(hidh, wh + WOFF_FC2, fc2_b, tokh, out, 256, 1024);
}